// round 14
// baseline (speedup 1.0000x reference)
#include <cuda_runtime.h>
#include <cstdint>
#include <cstddef>

// Problem constants (fixed by setup_inputs)
#define B_   2
#define S_   2048
#define H_   2048
#define NH_  32
#define NKV_ 8
#define HD_  64
#define QKVN 3072
#define BS_  (B_ * S_)   // 4096

// ---------------- scratch (device globals: allocation-free) ----------------
__device__ __align__(16) float g_qkv[(size_t)BS_ * QKVN];
__device__ __align__(16) float g_q[(size_t)BS_ * NH_ * HD_];
__device__ __align__(16) float g_k[(size_t)BS_ * NKV_ * HD_];
__device__ __align__(16) float g_v[(size_t)BS_ * NKV_ * HD_];    // [b][kh][d][s], tf32
__device__ __align__(16) float g_attn[(size_t)BS_ * NH_ * HD_];  // tf32-rounded
__device__ __align__(16) float g_hid_r[(size_t)BS_ * H_];        // tf32-rounded hidden
__device__ __align__(16) float g_wqkv_r[(size_t)QKVN * H_];      // tf32-rounded w_qkv
__device__ __align__(16) float g_wo_r[(size_t)H_ * H_];          // tf32-rounded w_o

// ---------------- helpers ----------------
__device__ __forceinline__ uint32_t smem_u32(const void* p) {
    uint32_t a;
    asm("{ .reg .u64 t; cvta.to.shared.u64 t, %1; cvt.u32.u64 %0, t; }" : "=r"(a) : "l"(p));
    return a;
}
__device__ __forceinline__ uint32_t tf32r(float f) {
    uint32_t r;
    asm("cvt.rna.tf32.f32 %0, %1;" : "=r"(r) : "f"(f));
    return r;
}
// m16n8k8 tf32 mma, fp32 accumulate (row.col)
__device__ __forceinline__ void mma8(float* d, const unsigned* a, unsigned b0, unsigned b1) {
    asm volatile(
        "mma.sync.aligned.m16n8k8.row.col.f32.tf32.tf32.f32 "
        "{%0,%1,%2,%3}, {%4,%5,%6,%7}, {%8,%9}, {%0,%1,%2,%3};"
        : "+f"(d[0]), "+f"(d[1]), "+f"(d[2]), "+f"(d[3])
        : "r"(a[0]), "r"(a[1]), "r"(a[2]), "r"(a[3]), "r"(b0), "r"(b1));
}
__device__ __forceinline__ void ldsm4(unsigned* r, uint32_t addr) {
    asm volatile("ldmatrix.sync.aligned.m8n8.x4.shared.b16 {%0,%1,%2,%3}, [%4];"
                 : "=r"(r[0]), "=r"(r[1]), "=r"(r[2]), "=r"(r[3]) : "r"(addr));
}
__device__ __forceinline__ void cpa16(uint32_t dst, const void* src) {
    asm volatile("cp.async.cg.shared.global [%0], [%1], 16;" :: "r"(dst), "l"(src) : "memory");
}
__device__ __forceinline__ void cpa_commit() {
    asm volatile("cp.async.commit_group;" ::: "memory");
}
__device__ __forceinline__ void cpa_wait0() {
    asm volatile("cp.async.wait_group 0;" ::: "memory");
}
__device__ __forceinline__ void cpa_wait1() {
    asm volatile("cp.async.wait_group 1;" ::: "memory");
}

// ---------------- round_copy: out = tf32_rna(in), vectorized ----------------
__global__ __launch_bounds__(256) void round_copy(
    const float* __restrict__ in, float* __restrict__ out, int n4)
{
    const int i = blockIdx.x * 256 + threadIdx.x;
    if (i < n4) {
        float4 v = ((const float4*)in)[i];
        uint4 u = make_uint4(tf32r(v.x), tf32r(v.y), tf32r(v.z), tf32r(v.w));
        ((uint4*)out)[i] = u;
    }
}

// ======================= tf32 mma GEMM: C = A[M,K] @ W[N,K]^T ===============
// 128x256 CTA tile, 512 threads, 16 warps (2x8 of 64x32), BK=32 stages,
// 3-stage cp.async (144KB dynamic smem), pre-rounded tf32 operands.
// Per stage: mma = 2048 cyc vs smem = ~1920 cyc -> compute-bound; barrier
// count per output halved vs the 128x128 tile. Warp tile unchanged (64 accs).
#define GA_STAGE 16384u                 // 128*32*4
#define GB_STAGE 32768u                 // 256*32*4
#define G_SMEM_BYTES (3 * (GA_STAGE + GB_STAGE))   // 147456 = 144KB

__device__ __forceinline__ uint32_t gaddrA32(uint32_t base, int m0, int ks, int lane) {
    int sub = lane >> 3;
    int row = m0 + (sub & 1) * 8 + (lane & 7);
    int kc  = 2 * ks + (sub >> 1);
    return base + (uint32_t)(row * 32 + ((kc ^ (row & 7)) << 2)) * 4u;
}
__device__ __forceinline__ uint32_t gaddrB32(uint32_t base, int n0, int ks, int lane) {
    int sub = lane >> 3;
    int row = n0 + (sub >> 1) * 8 + (lane & 7);
    int kc  = 2 * ks + (sub & 1);
    return base + (uint32_t)(row * 32 + ((kc ^ (row & 7)) << 2)) * 4u;
}

__global__ __launch_bounds__(512) void gemm_mma(
    const float* __restrict__ A, const float* __restrict__ W,
    float* __restrict__ C, int M, int N, int K)
{
    extern __shared__ __align__(16) char gsm[];
    const uint32_t gbase = smem_u32(gsm);
    const uint32_t asb[3] = { gbase, gbase + GA_STAGE, gbase + 2 * GA_STAGE };
    const uint32_t b0b = gbase + 3 * GA_STAGE;
    const uint32_t bsb[3] = { b0b, b0b + GB_STAGE, b0b + 2 * GB_STAGE };

    const int tid = threadIdx.x, lane = tid & 31, wid = tid >> 5;
    const int bm = blockIdx.y * 128, bn = blockIdx.x * 256;
    const int wm = (wid & 1) * 64, wn = (wid >> 1) * 32;

    // loaders: A rows 0..127 (4 thr/row, 2 chunks each); B rows 0..255 (2 thr/row, 4 chunks)
    const int tra = tid >> 2;
    const int ca0 = (tid & 3) * 2;
    const int trb = tid >> 1;
    const int cb0 = (tid & 1) * 4;
    const float* Ap = A + (size_t)(bm + tra) * K + ca0 * 4;
    const float* Wp = W + (size_t)(bn + trb) * K + cb0 * 4;
    uint32_t soA[2], soB[4];
#pragma unroll
    for (int l = 0; l < 2; l++)
        soA[l] = (uint32_t)(tra * 32 + (((ca0 + l) ^ (tra & 7)) << 2)) * 4u;
#pragma unroll
    for (int l = 0; l < 4; l++)
        soB[l] = (uint32_t)(trb * 32 + (((cb0 + l) ^ (trb & 7)) << 2)) * 4u;

    float acc[16][4];
#pragma unroll
    for (int i = 0; i < 16; i++)
#pragma unroll
        for (int j = 0; j < 4; j++) acc[i][j] = 0.0f;

    const int T = K >> 5;    // BK = 32

    // ---- prologue: issue stages 0 and 1 ----
#pragma unroll
    for (int s = 0; s < 2; s++) {
        const float* a = Ap + s * 32;
        const float* w = Wp + s * 32;
#pragma unroll
        for (int l = 0; l < 2; l++) cpa16(asb[s] + soA[l], a + l * 4);
#pragma unroll
        for (int l = 0; l < 4; l++) cpa16(bsb[s] + soB[l], w + l * 4);
        cpa_commit();
    }

    for (int t = 0; t < T; t++) {
        cpa_wait1();
        __syncthreads();

        if (t + 2 < T) {
            const int s = (t + 2) % 3;
            const float* a = Ap + (t + 2) * 32;
            const float* w = Wp + (t + 2) * 32;
#pragma unroll
            for (int l = 0; l < 2; l++) cpa16(asb[s] + soA[l], a + l * 4);
#pragma unroll
            for (int l = 0; l < 4; l++) cpa16(bsb[s] + soB[l], w + l * 4);
            cpa_commit();
        }

        const int buf = t % 3;
#pragma unroll
        for (int ks = 0; ks < 4; ks++) {
            unsigned af[4][4], bf[2][4];
#pragma unroll
            for (int mt = 0; mt < 4; mt++)
                ldsm4(af[mt], gaddrA32(asb[buf], wm + mt * 16, ks, lane));
#pragma unroll
            for (int bp = 0; bp < 2; bp++)
                ldsm4(bf[bp], gaddrB32(bsb[buf], wn + bp * 16, ks, lane));
#pragma unroll
            for (int mt = 0; mt < 4; mt++)
#pragma unroll
                for (int nt = 0; nt < 4; nt++)
                    mma8(acc[mt * 4 + nt], af[mt],
                         bf[nt >> 1][(nt & 1) * 2], bf[nt >> 1][(nt & 1) * 2 + 1]);
        }
    }

    // epilogue
#pragma unroll
    for (int mt = 0; mt < 4; mt++) {
        const int rA = bm + wm + mt * 16 + (lane >> 2);
        float* cA = C + (size_t)rA * N + bn + wn + (lane & 3) * 2;
        float* cB = cA + 8 * (size_t)N;
#pragma unroll
        for (int nt = 0; nt < 4; nt++) {
            *(float2*)(cA + nt * 8) = make_float2(acc[mt * 4 + nt][0], acc[mt * 4 + nt][1]);
            *(float2*)(cB + nt * 8) = make_float2(acc[mt * 4 + nt][2], acc[mt * 4 + nt][3]);
        }
    }
}

// ---------------- fused per-head LayerNorm + partial NeoX RoPE ----------------
__global__ __launch_bounds__(256) void ln_rope(
    const float* __restrict__ qkv, const int* __restrict__ pos_ids,
    const float* __restrict__ qw, const float* __restrict__ kw,
    float* __restrict__ qo, float* __restrict__ ko)
{
    const int wid = threadIdx.x >> 5;
    const int lane = threadIdx.x & 31;
    const int bs = blockIdx.x / 5;
    const int head = (blockIdx.x % 5) * 8 + wid;   // 0..39 (32 Q + 8 K)

    const float* src = qkv + (size_t)bs * QKVN + head * HD_;
    float v0 = src[lane], v1 = src[lane + 32];

    float s = v0 + v1;
#pragma unroll
    for (int m = 16; m; m >>= 1) s += __shfl_xor_sync(~0u, s, m);
    const float mu = s * (1.0f / 64.0f);
    const float d0 = v0 - mu, d1 = v1 - mu;
    float vs = d0 * d0 + d1 * d1;
#pragma unroll
    for (int m = 16; m; m >>= 1) vs += __shfl_xor_sync(~0u, vs, m);
    const float inv = rsqrtf(vs * (1.0f / 64.0f) + 1e-5f);

    const float* w = (head < NH_) ? (qw + head * HD_) : (kw + (head - NH_) * HD_);
    float n0 = d0 * inv * w[lane];
    float n1 = d1 * inv * w[lane + 32];

    const float p = (float)pos_ids[bs];
    const float partner = __shfl_xor_sync(~0u, n0, 8);
    if (lane < 16) {
        const int i = lane & 7;
        const float invf = powf(10000.0f, -(float)i * 0.125f);
        const float ang = p * invf;
        const float c = cosf(ang), sn = sinf(ang);
        n0 = (lane < 8) ? (n0 * c - partner * sn) : (n0 * c + partner * sn);
    }
    const float sc = (head < NH_) ? 0.125f : 1.0f;   // HEAD_DIM^-0.5 folded into Q
    n0 = __uint_as_float(tf32r(n0 * sc));
    n1 = __uint_as_float(tf32r(n1 * sc));

    if (head < NH_) {
        float* dst = qo + ((size_t)bs * NH_ + head) * HD_;
        dst[lane] = n0; dst[lane + 32] = n1;
    } else {
        float* dst = ko + ((size_t)bs * NKV_ + (head - NH_)) * HD_;
        dst[lane] = n0; dst[lane + 32] = n1;
    }
}

// ---------------- prep_v: transpose V to [b][kh][d][s] with tf32 round -------
__global__ __launch_bounds__(256) void prep_v(
    const float* __restrict__ qkv, float* __restrict__ V)
{
    __shared__ float ts[64][65];
    const int bkh = blockIdx.y;             // 0..15
    const int b = bkh >> 3, kh = bkh & 7;
    const int s0 = blockIdx.x * 64;
    const int r  = threadIdx.x >> 2;        // 0..63
    const int c0 = (threadIdx.x & 3) * 16;

    const float* src = qkv + (size_t)(b * S_ + s0 + r) * QKVN + 2560 + kh * 64 + c0;
#pragma unroll
    for (int l = 0; l < 4; l++) {
        float4 v = *(const float4*)(src + l * 4);
        ts[r][c0 + l * 4 + 0] = __uint_as_float(tf32r(v.x));
        ts[r][c0 + l * 4 + 1] = __uint_as_float(tf32r(v.y));
        ts[r][c0 + l * 4 + 2] = __uint_as_float(tf32r(v.z));
        ts[r][c0 + l * 4 + 3] = __uint_as_float(tf32r(v.w));
    }
    __syncthreads();

    const int d  = threadIdx.x >> 2;
    const int sc = (threadIdx.x & 3) * 16;
    float* dst = V + ((size_t)(b * NKV_ + kh) * HD_ + d) * S_ + s0 + sc;
#pragma unroll
    for (int l = 0; l < 4; l++) {
        float4 w = make_float4(ts[sc + l * 4 + 0][d], ts[sc + l * 4 + 1][d],
                               ts[sc + l * 4 + 2][d], ts[sc + l * 4 + 3][d]);
        *(float4*)(dst + l * 4) = w;
    }
}

// ======================= flash attention v4 (tf32 mma, warp-owns-rows) =======
// (unchanged from R13)
#define ATTN_SMEM_BYTES 98304

__global__ __launch_bounds__(256, 2) void attn_mma4(
    const float* __restrict__ Q, const float* __restrict__ Kg,
    const float* __restrict__ Vg, float* __restrict__ O)
{
    extern __shared__ __align__(16) char smraw[];
    float* Qs = (float*)smraw;                              // [128][64] 32KB
    const uint32_t qsb = smem_u32(smraw);
    const uint32_t ksb[2] = { qsb + 32768u, qsb + 49152u };
    const uint32_t vtb[2] = { qsb + 65536u, qsb + 81920u };

    const int qt = (int)gridDim.x - 1 - (int)blockIdx.x;    // heavy tiles first
    const int bh = blockIdx.y;
    const int b = bh >> 5, h = bh & 31, kh = h >> 2;
    const int tid = threadIdx.x, lane = tid & 31, wid = tid >> 5;
    const int wm = wid * 16;                                // warp's 16 rows
    const int sub = lane >> 3;

    const int cr = tid >> 2;
    const int cb = (tid & 3) * 4;
    const int crl = cr & 7;
    const int crp = (cr & 56) | ((crl & 3) * 2 + (crl >> 2));   // permuted K row
    const uint32_t kswz = (uint32_t)(crp & 7);
    const uint32_t vswz = (uint32_t)((cr & 7) ^ ((cr >> 4) & 3));
    const float* vrow = Vg + ((size_t)(b * NKV_ + kh) * HD_ + cr) * S_;

    // ---- issue KV tile 0 (overlaps the Q load) ----
    {
        const float* krow = Kg + ((size_t)(b * S_ + cr) * NKV_ + kh) * HD_;
#pragma unroll
        for (int l = 0; l < 4; l++) {
            const int c = cb + l;
            cpa16(ksb[0] + crp * 256u + ((uint32_t)(c ^ kswz) << 4), krow + c * 4);
            cpa16(vtb[0] + cr * 256u + ((uint32_t)(c ^ vswz) << 4), vrow + c * 4);
        }
        cpa_commit();
    }

    // ---- load Q tile 128x64 ----
    {
        const int r = tid >> 1;
        const int hb = (tid & 1) * 8;
        const float* qp = Q + ((size_t)(b * S_ + qt * 128 + r) * NH_ + h) * HD_ + hb * 4;
#pragma unroll
        for (int l = 0; l < 8; l++) {
            float4 v = *(const float4*)(qp + l * 4);
            *(float4*)(Qs + r * 64 + (((hb + l) ^ (r & 7)) << 2)) = v;
        }
    }

    float acc_o[8][4];
#pragma unroll
    for (int n8 = 0; n8 < 8; n8++)
#pragma unroll
        for (int e = 0; e < 4; e++) acc_o[n8][e] = 0.0f;
    float mA = -1e30f, mB = -1e30f, lA = 0.0f, lB = 0.0f;

    cpa_wait0();
    __syncthreads();

    const int ktmax = 2 * qt + 1;
    for (int kt = 0; kt <= ktmax; kt++) {
        const int buf = kt & 1;

        if (kt < ktmax) {
            const int nb = buf ^ 1;
            const float* krow = Kg + ((size_t)(b * S_ + (kt + 1) * 64 + cr) * NKV_ + kh) * HD_;
            const float* vsrc = vrow + (kt + 1) * 64;
#pragma unroll
            for (int l = 0; l < 4; l++) {
                const int c = cb + l;
                cpa16(ksb[nb] + crp * 256u + ((uint32_t)(c ^ kswz) << 4), krow + c * 4);
                cpa16(vtb[nb] + cr * 256u + ((uint32_t)(c ^ vswz) << 4), vsrc + c * 4);
            }
            cpa_commit();
        }

        float sacc[8][4];
#pragma unroll
        for (int nt = 0; nt < 8; nt++)
#pragma unroll
            for (int e = 0; e < 4; e++) sacc[nt][e] = 0.0f;
#pragma unroll
        for (int ks = 0; ks < 8; ks++) {
            unsigned qf[4];
            {
                const int row = wm + (sub & 1) * 8 + (lane & 7);
                const int kc = 2 * ks + (sub >> 1);
                ldsm4(qf, qsb + (uint32_t)(row * 64 + ((kc ^ (row & 7)) << 2)) * 4u);
            }
#pragma unroll
            for (int bp = 0; bp < 4; bp++) {
                unsigned kbf[4];
                const int row = bp * 16 + (sub >> 1) * 8 + (lane & 7);
                const int kc = 2 * ks + (sub & 1);
                ldsm4(kbf, ksb[buf] + (uint32_t)(row * 64 + ((kc ^ (row & 7)) << 2)) * 4u);
                mma8(sacc[bp * 2],     qf, kbf[0], kbf[1]);
                mma8(sacc[bp * 2 + 1], qf, kbf[2], kbf[3]);
            }
        }

        const int koff = kt * 64 - qt * 128;
        if (koff >= 0) {
            const int rA = wm + (lane >> 2);
            const int rB = rA + 8;
#pragma unroll
            for (int nt = 0; nt < 8; nt++) {
                const int k0 = koff + nt * 8 + (lane & 3);
                const int k1 = k0 + 4;
                if (k0 > rA) sacc[nt][0] = -1e30f;
                if (k1 > rA) sacc[nt][1] = -1e30f;
                if (k0 > rB) sacc[nt][2] = -1e30f;
                if (k1 > rB) sacc[nt][3] = -1e30f;
            }
        }

        {
            float hmA = -1e30f, hmB = -1e30f;
#pragma unroll
            for (int nt = 0; nt < 8; nt++) {
                hmA = fmaxf(hmA, fmaxf(sacc[nt][0], sacc[nt][1]));
                hmB = fmaxf(hmB, fmaxf(sacc[nt][2], sacc[nt][3]));
            }
            hmA = fmaxf(hmA, __shfl_xor_sync(~0u, hmA, 1));
            hmA = fmaxf(hmA, __shfl_xor_sync(~0u, hmA, 2));
            hmB = fmaxf(hmB, __shfl_xor_sync(~0u, hmB, 1));
            hmB = fmaxf(hmB, __shfl_xor_sync(~0u, hmB, 2));
            const float mnA = fmaxf(mA, hmA);
            const float mnB = fmaxf(mB, hmB);
            const float alA = __expf(mA - mnA);
            const float alB = __expf(mB - mnB);
            mA = mnA; mB = mnB;

            float hsA = 0.0f, hsB = 0.0f;
#pragma unroll
            for (int nt = 0; nt < 8; nt++) {
                const float p0 = __expf(sacc[nt][0] - mnA);
                const float p1 = __expf(sacc[nt][1] - mnA);
                const float p2 = __expf(sacc[nt][2] - mnB);
                const float p3 = __expf(sacc[nt][3] - mnB);
                hsA += p0 + p1; hsB += p2 + p3;
                sacc[nt][0] = __uint_as_float(tf32r(p0));
                sacc[nt][1] = __uint_as_float(tf32r(p1));
                sacc[nt][2] = __uint_as_float(tf32r(p2));
                sacc[nt][3] = __uint_as_float(tf32r(p3));
            }
            hsA += __shfl_xor_sync(~0u, hsA, 1); hsA += __shfl_xor_sync(~0u, hsA, 2);
            hsB += __shfl_xor_sync(~0u, hsB, 1); hsB += __shfl_xor_sync(~0u, hsB, 2);
            lA = lA * alA + hsA;
            lB = lB * alB + hsB;

#pragma unroll
            for (int n8 = 0; n8 < 8; n8++) {
                acc_o[n8][0] *= alA; acc_o[n8][1] *= alA;
                acc_o[n8][2] *= alB; acc_o[n8][3] *= alB;
            }
        }

#pragma unroll
        for (int jc = 0; jc < 8; jc++) {
            const unsigned* u = (const unsigned*)sacc[jc];
            const unsigned pa[4] = { u[0], u[2], u[1], u[3] };
#pragma unroll
            for (int bp = 0; bp < 4; bp++) {
                unsigned vb[4];
                const int d = bp * 16 + (sub >> 1) * 8 + (lane & 7);
                const int jj = 2 * jc + (sub & 1);
                const int ch = jj ^ (d & 7) ^ ((d >> 4) & 3);
                ldsm4(vb, vtb[buf] + (uint32_t)(d * 64 + (ch << 2)) * 4u);
                mma8(acc_o[bp * 2],     pa, vb[0], vb[1]);
                mma8(acc_o[bp * 2 + 1], pa, vb[2], vb[3]);
            }
        }

        cpa_wait0();
        __syncthreads();
    }

    // ---- epilogue: direct per-warp store, tf32-rounded for gemm2 ----
    {
        const int rA = wm + (lane >> 2);
        const int rB = rA + 8;
        const float liA = 1.0f / lA;
        const float liB = 1.0f / lB;
        float* oA = O + (size_t)(b * S_ + qt * 128 + rA) * H_ + h * HD_ + (lane & 3) * 2;
        float* oB = O + (size_t)(b * S_ + qt * 128 + rB) * H_ + h * HD_ + (lane & 3) * 2;
#pragma unroll
        for (int n8 = 0; n8 < 8; n8++) {
            *(float2*)(oA + n8 * 8) = make_float2(
                __uint_as_float(tf32r(acc_o[n8][0] * liA)),
                __uint_as_float(tf32r(acc_o[n8][1] * liA)));
            *(float2*)(oB + n8 * 8) = make_float2(
                __uint_as_float(tf32r(acc_o[n8][2] * liB)),
                __uint_as_float(tf32r(acc_o[n8][3] * liB)));
        }
    }
}

// ---------------- launch ----------------
extern "C" void kernel_launch(void* const* d_in, const int* in_sizes, int n_in,
                              void* d_out, int out_size)
{
    const int*   pos  = (const int*)d_in[0];
    const float* hid  = (const float*)d_in[1];
    const float* wqkv = (const float*)d_in[2];
    const float* qw   = (const float*)d_in[3];
    const float* kw   = (const float*)d_in[4];
    const float* wo   = (const float*)d_in[5];
    float* out = (float*)d_out;

    float *qkv, *q, *k, *v, *attnb, *hid_r, *wqkv_r, *wo_r;
    cudaGetSymbolAddress((void**)&qkv,    g_qkv);
    cudaGetSymbolAddress((void**)&q,      g_q);
    cudaGetSymbolAddress((void**)&k,      g_k);
    cudaGetSymbolAddress((void**)&v,      g_v);
    cudaGetSymbolAddress((void**)&attnb,  g_attn);
    cudaGetSymbolAddress((void**)&hid_r,  g_hid_r);
    cudaGetSymbolAddress((void**)&wqkv_r, g_wqkv_r);
    cudaGetSymbolAddress((void**)&wo_r,   g_wo_r);

    cudaFuncSetAttribute(gemm_mma,
                         cudaFuncAttributeMaxDynamicSharedMemorySize, G_SMEM_BYTES);
    cudaFuncSetAttribute(attn_mma4,
                         cudaFuncAttributeMaxDynamicSharedMemorySize, ATTN_SMEM_BYTES);

    // 0) tf32-round the GEMM operands once
    const int n4_hid  = (BS_ * H_) / 4;
    const int n4_wqkv = (QKVN * H_) / 4;
    const int n4_wo   = (H_ * H_) / 4;
    round_copy<<<(n4_hid  + 255) / 256, 256>>>(hid,  hid_r,  n4_hid);
    round_copy<<<(n4_wqkv + 255) / 256, 256>>>(wqkv, wqkv_r, n4_wqkv);
    round_copy<<<(n4_wo   + 255) / 256, 256>>>(wo,   wo_r,   n4_wo);

    // 1) qkv = hidden @ w_qkv^T   (128x256 CTA tile, 512 threads)
    dim3 g1(QKVN / 256, BS_ / 128);
    gemm_mma<<<g1, 512, G_SMEM_BYTES>>>(hid_r, wqkv_r, qkv, BS_, QKVN, H_);

    // 2a) per-head LN + partial RoPE
    ln_rope<<<BS_ * 5, 256>>>(qkv, pos, qw, kw, q, k);
    // 2b) transpose V to [b][kh][d][s] (tf32)
    prep_v<<<dim3(S_ / 64, B_ * NKV_), 256>>>(qkv, v);

    // 3) causal GQA attention (v4)
    attn_mma4<<<dim3(S_ / 128, B_ * NH_), 256, ATTN_SMEM_BYTES>>>(q, k, v, attnb);

    // 4) out = attn @ w_o^T
    dim3 g2(H_ / 256, BS_ / 128);
    gemm_mma<<<g2, 512, G_SMEM_BYTES>>>(attnb, wo_r, out, BS_, H_, H_);
}

// round 15
// speedup vs baseline: 1.4381x; 1.4381x over previous
#include <cuda_runtime.h>
#include <cuda_fp16.h>
#include <cstdint>
#include <cstddef>

// Problem constants (fixed by setup_inputs)
#define B_   2
#define S_   2048
#define H_   2048
#define NH_  32
#define NKV_ 8
#define HD_  64
#define QKVN 3072
#define BS_  (B_ * S_)   // 4096

// ---------------- scratch (device globals: allocation-free) ----------------
__device__ __align__(16) float  g_qkv[(size_t)BS_ * QKVN];
__device__ __align__(16) float  g_q[(size_t)BS_ * NH_ * HD_];
__device__ __align__(16) float  g_k[(size_t)BS_ * NKV_ * HD_];
__device__ __align__(16) float  g_v[(size_t)BS_ * NKV_ * HD_];   // [b][kh][d][s], tf32
__device__ __align__(16) __half g_attn_h[(size_t)BS_ * NH_ * HD_]; // fp16 attn out
__device__ __align__(16) __half g_hid_h[(size_t)BS_ * H_];       // fp16 hidden
__device__ __align__(16) __half g_wqkv_h[(size_t)QKVN * H_];     // fp16 w_qkv
__device__ __align__(16) __half g_wo_h[(size_t)H_ * H_];         // fp16 w_o

// ---------------- helpers ----------------
__device__ __forceinline__ uint32_t smem_u32(const void* p) {
    uint32_t a;
    asm("{ .reg .u64 t; cvta.to.shared.u64 t, %1; cvt.u32.u64 %0, t; }" : "=r"(a) : "l"(p));
    return a;
}
__device__ __forceinline__ uint32_t tf32r(float f) {
    uint32_t r;
    asm("cvt.rna.tf32.f32 %0, %1;" : "=r"(r) : "f"(f));
    return r;
}
// m16n8k8 tf32 mma (attention)
__device__ __forceinline__ void mma8(float* d, const unsigned* a, unsigned b0, unsigned b1) {
    asm volatile(
        "mma.sync.aligned.m16n8k8.row.col.f32.tf32.tf32.f32 "
        "{%0,%1,%2,%3}, {%4,%5,%6,%7}, {%8,%9}, {%0,%1,%2,%3};"
        : "+f"(d[0]), "+f"(d[1]), "+f"(d[2]), "+f"(d[3])
        : "r"(a[0]), "r"(a[1]), "r"(a[2]), "r"(a[3]), "r"(b0), "r"(b1));
}
// m16n8k16 fp16 mma, fp32 accumulate (GEMMs)
__device__ __forceinline__ void mma16h(float* d, const unsigned* a, unsigned b0, unsigned b1) {
    asm volatile(
        "mma.sync.aligned.m16n8k16.row.col.f32.f16.f16.f32 "
        "{%0,%1,%2,%3}, {%4,%5,%6,%7}, {%8,%9}, {%0,%1,%2,%3};"
        : "+f"(d[0]), "+f"(d[1]), "+f"(d[2]), "+f"(d[3])
        : "r"(a[0]), "r"(a[1]), "r"(a[2]), "r"(a[3]), "r"(b0), "r"(b1));
}
__device__ __forceinline__ void ldsm4(unsigned* r, uint32_t addr) {
    asm volatile("ldmatrix.sync.aligned.m8n8.x4.shared.b16 {%0,%1,%2,%3}, [%4];"
                 : "=r"(r[0]), "=r"(r[1]), "=r"(r[2]), "=r"(r[3]) : "r"(addr));
}
__device__ __forceinline__ void cpa16(uint32_t dst, const void* src) {
    asm volatile("cp.async.cg.shared.global [%0], [%1], 16;" :: "r"(dst), "l"(src) : "memory");
}
__device__ __forceinline__ void cpa_commit() {
    asm volatile("cp.async.commit_group;" ::: "memory");
}
__device__ __forceinline__ void cpa_wait0() {
    asm volatile("cp.async.wait_group 0;" ::: "memory");
}
__device__ __forceinline__ void cpa_wait1() {
    asm volatile("cp.async.wait_group 1;" ::: "memory");
}

// ---------------- round_half: out = fp16(in), vectorized ----------------
__global__ __launch_bounds__(256) void round_half(
    const float* __restrict__ in, __half* __restrict__ out, int n4)
{
    const int i = blockIdx.x * 256 + threadIdx.x;
    if (i < n4) {
        float4 v = ((const float4*)in)[i];
        __half2 h0; h0.x = __float2half_rn(v.x); h0.y = __float2half_rn(v.y);
        __half2 h1; h1.x = __float2half_rn(v.z); h1.y = __float2half_rn(v.w);
        ((__half2*)out)[i * 2]     = h0;
        ((__half2*)out)[i * 2 + 1] = h1;
    }
}

// ================ fp16 mma GEMM: C = A[M,K] @ W[N,K]^T (fp32 out) ===========
// 128x128 CTA tile, 8 warps (2x4 of 64x32), BK=32 stages, 3-stage cp.async.
// Smem stage = [128 rows][32 halfs] (64B rows); chunk swizzle c ^ ((row>>1)&3)
// -> ldsm slot = 4*(row&1)+swz covers all 8 over any 8 consecutive rows.
// Per stage/warp: 12 ldsm + 32 mma (half the tf32 instruction count).
__device__ __forceinline__ uint32_t haddrA(uint32_t base, int m0, int ks, int lane) {
    int sub = lane >> 3;
    int row = m0 + (sub & 1) * 8 + (lane & 7);
    int c   = ks * 2 + (sub >> 1);
    return base + (uint32_t)(row * 64 + ((c ^ ((row >> 1) & 3)) << 4));
}
__device__ __forceinline__ uint32_t haddrB(uint32_t base, int n0, int ks, int lane) {
    int sub = lane >> 3;
    int row = n0 + (sub >> 1) * 8 + (lane & 7);
    int c   = ks * 2 + (sub & 1);
    return base + (uint32_t)(row * 64 + ((c ^ ((row >> 1) & 3)) << 4));
}

__global__ __launch_bounds__(256, 2) void gemm_h(
    const __half* __restrict__ A, const __half* __restrict__ W,
    float* __restrict__ C, int M, int N, int K)
{
    __shared__ __align__(16) __half As[3][128 * 32];   // 3 x 8KB
    __shared__ __align__(16) __half Bs[3][128 * 32];   // 3 x 8KB
    const uint32_t asb[3] = { smem_u32(As[0]), smem_u32(As[1]), smem_u32(As[2]) };
    const uint32_t bsb[3] = { smem_u32(Bs[0]), smem_u32(Bs[1]), smem_u32(Bs[2]) };

    const int tid = threadIdx.x, lane = tid & 31, wid = tid >> 5;
    const int bm = blockIdx.y * 128, bn = blockIdx.x * 128;
    const int wm = (wid & 1) * 64, wn = (wid >> 1) * 32;

    // loader: row = tid>>1 (0..127), chunks c0, c0+1 (16B = 8 halfs each)
    const int tr = tid >> 1;
    const int c0 = (tid & 1) * 2;
    const __half* Ap = A + (size_t)(bm + tr) * K + c0 * 8;
    const __half* Wp = W + (size_t)(bn + tr) * K + c0 * 8;
    uint32_t so[2];
#pragma unroll
    for (int l = 0; l < 2; l++)
        so[l] = (uint32_t)(tr * 64 + (((c0 + l) ^ ((tr >> 1) & 3)) << 4));

    float acc[16][4];
#pragma unroll
    for (int i = 0; i < 16; i++)
#pragma unroll
        for (int j = 0; j < 4; j++) acc[i][j] = 0.0f;

    const int T = K >> 5;    // BK = 32

    // ---- prologue: issue stages 0 and 1 ----
#pragma unroll
    for (int s = 0; s < 2; s++) {
        const __half* a = Ap + s * 32;
        const __half* w = Wp + s * 32;
#pragma unroll
        for (int l = 0; l < 2; l++) {
            cpa16(asb[s] + so[l], a + l * 8);
            cpa16(bsb[s] + so[l], w + l * 8);
        }
        cpa_commit();
    }

    for (int t = 0; t < T; t++) {
        cpa_wait1();
        __syncthreads();

        if (t + 2 < T) {
            const int s = (t + 2) % 3;
            const __half* a = Ap + (t + 2) * 32;
            const __half* w = Wp + (t + 2) * 32;
#pragma unroll
            for (int l = 0; l < 2; l++) {
                cpa16(asb[s] + so[l], a + l * 8);
                cpa16(bsb[s] + so[l], w + l * 8);
            }
            cpa_commit();
        }

        const int buf = t % 3;
#pragma unroll
        for (int ks = 0; ks < 2; ks++) {   // 2 x K16 per stage
            unsigned af[4][4], bf[2][4];
#pragma unroll
            for (int mt = 0; mt < 4; mt++)
                ldsm4(af[mt], haddrA(asb[buf], wm + mt * 16, ks, lane));
#pragma unroll
            for (int bp = 0; bp < 2; bp++)
                ldsm4(bf[bp], haddrB(bsb[buf], wn + bp * 16, ks, lane));
#pragma unroll
            for (int mt = 0; mt < 4; mt++)
#pragma unroll
                for (int bp = 0; bp < 2; bp++) {
                    mma16h(acc[mt * 4 + bp * 2],     af[mt], bf[bp][0], bf[bp][1]);
                    mma16h(acc[mt * 4 + bp * 2 + 1], af[mt], bf[bp][2], bf[bp][3]);
                }
        }
    }

    // epilogue (fp32 out)
#pragma unroll
    for (int mt = 0; mt < 4; mt++) {
        const int rA = bm + wm + mt * 16 + (lane >> 2);
        float* cA = C + (size_t)rA * N + bn + wn + (lane & 3) * 2;
        float* cB = cA + 8 * (size_t)N;
#pragma unroll
        for (int nt = 0; nt < 4; nt++) {
            *(float2*)(cA + nt * 8) = make_float2(acc[mt * 4 + nt][0], acc[mt * 4 + nt][1]);
            *(float2*)(cB + nt * 8) = make_float2(acc[mt * 4 + nt][2], acc[mt * 4 + nt][3]);
        }
    }
}

// ---------------- fused per-head LayerNorm + partial NeoX RoPE ----------------
__global__ __launch_bounds__(256) void ln_rope(
    const float* __restrict__ qkv, const int* __restrict__ pos_ids,
    const float* __restrict__ qw, const float* __restrict__ kw,
    float* __restrict__ qo, float* __restrict__ ko)
{
    const int wid = threadIdx.x >> 5;
    const int lane = threadIdx.x & 31;
    const int bs = blockIdx.x / 5;
    const int head = (blockIdx.x % 5) * 8 + wid;   // 0..39 (32 Q + 8 K)

    const float* src = qkv + (size_t)bs * QKVN + head * HD_;
    float v0 = src[lane], v1 = src[lane + 32];

    float s = v0 + v1;
#pragma unroll
    for (int m = 16; m; m >>= 1) s += __shfl_xor_sync(~0u, s, m);
    const float mu = s * (1.0f / 64.0f);
    const float d0 = v0 - mu, d1 = v1 - mu;
    float vs = d0 * d0 + d1 * d1;
#pragma unroll
    for (int m = 16; m; m >>= 1) vs += __shfl_xor_sync(~0u, vs, m);
    const float inv = rsqrtf(vs * (1.0f / 64.0f) + 1e-5f);

    const float* w = (head < NH_) ? (qw + head * HD_) : (kw + (head - NH_) * HD_);
    float n0 = d0 * inv * w[lane];
    float n1 = d1 * inv * w[lane + 32];

    const float p = (float)pos_ids[bs];
    const float partner = __shfl_xor_sync(~0u, n0, 8);
    if (lane < 16) {
        const int i = lane & 7;
        const float invf = powf(10000.0f, -(float)i * 0.125f);
        const float ang = p * invf;
        const float c = cosf(ang), sn = sinf(ang);
        n0 = (lane < 8) ? (n0 * c - partner * sn) : (n0 * c + partner * sn);
    }
    const float sc = (head < NH_) ? 0.125f : 1.0f;   // HEAD_DIM^-0.5 folded into Q
    n0 = __uint_as_float(tf32r(n0 * sc));
    n1 = __uint_as_float(tf32r(n1 * sc));

    if (head < NH_) {
        float* dst = qo + ((size_t)bs * NH_ + head) * HD_;
        dst[lane] = n0; dst[lane + 32] = n1;
    } else {
        float* dst = ko + ((size_t)bs * NKV_ + (head - NH_)) * HD_;
        dst[lane] = n0; dst[lane + 32] = n1;
    }
}

// ---------------- prep_v: transpose V to [b][kh][d][s] with tf32 round -------
__global__ __launch_bounds__(256) void prep_v(
    const float* __restrict__ qkv, float* __restrict__ V)
{
    __shared__ float ts[64][65];
    const int bkh = blockIdx.y;             // 0..15
    const int b = bkh >> 3, kh = bkh & 7;
    const int s0 = blockIdx.x * 64;
    const int r  = threadIdx.x >> 2;        // 0..63
    const int c0 = (threadIdx.x & 3) * 16;

    const float* src = qkv + (size_t)(b * S_ + s0 + r) * QKVN + 2560 + kh * 64 + c0;
#pragma unroll
    for (int l = 0; l < 4; l++) {
        float4 v = *(const float4*)(src + l * 4);
        ts[r][c0 + l * 4 + 0] = __uint_as_float(tf32r(v.x));
        ts[r][c0 + l * 4 + 1] = __uint_as_float(tf32r(v.y));
        ts[r][c0 + l * 4 + 2] = __uint_as_float(tf32r(v.z));
        ts[r][c0 + l * 4 + 3] = __uint_as_float(tf32r(v.w));
    }
    __syncthreads();

    const int d  = threadIdx.x >> 2;
    const int sc = (threadIdx.x & 3) * 16;
    float* dst = V + ((size_t)(b * NKV_ + kh) * HD_ + d) * S_ + s0 + sc;
#pragma unroll
    for (int l = 0; l < 4; l++) {
        float4 w = make_float4(ts[sc + l * 4 + 0][d], ts[sc + l * 4 + 1][d],
                               ts[sc + l * 4 + 2][d], ts[sc + l * 4 + 3][d]);
        *(float4*)(dst + l * 4) = w;
    }
}

// ======================= flash attention v4 (tf32 mma, warp-owns-rows) =======
// (R13 design; epilogue now emits fp16 for the fp16 gemm2)
#define ATTN_SMEM_BYTES 98304

__global__ __launch_bounds__(256, 2) void attn_mma4(
    const float* __restrict__ Q, const float* __restrict__ Kg,
    const float* __restrict__ Vg, __half* __restrict__ O)
{
    extern __shared__ __align__(16) char smraw[];
    float* Qs = (float*)smraw;                              // [128][64] 32KB
    const uint32_t qsb = smem_u32(smraw);
    const uint32_t ksb[2] = { qsb + 32768u, qsb + 49152u };
    const uint32_t vtb[2] = { qsb + 65536u, qsb + 81920u };

    const int qt = (int)gridDim.x - 1 - (int)blockIdx.x;    // heavy tiles first
    const int bh = blockIdx.y;
    const int b = bh >> 5, h = bh & 31, kh = h >> 2;
    const int tid = threadIdx.x, lane = tid & 31, wid = tid >> 5;
    const int wm = wid * 16;                                // warp's 16 rows
    const int sub = lane >> 3;

    const int cr = tid >> 2;
    const int cb = (tid & 3) * 4;
    const int crl = cr & 7;
    const int crp = (cr & 56) | ((crl & 3) * 2 + (crl >> 2));   // permuted K row
    const uint32_t kswz = (uint32_t)(crp & 7);
    const uint32_t vswz = (uint32_t)((cr & 7) ^ ((cr >> 4) & 3));
    const float* vrow = Vg + ((size_t)(b * NKV_ + kh) * HD_ + cr) * S_;

    // ---- issue KV tile 0 (overlaps the Q load) ----
    {
        const float* krow = Kg + ((size_t)(b * S_ + cr) * NKV_ + kh) * HD_;
#pragma unroll
        for (int l = 0; l < 4; l++) {
            const int c = cb + l;
            cpa16(ksb[0] + crp * 256u + ((uint32_t)(c ^ kswz) << 4), krow + c * 4);
            cpa16(vtb[0] + cr * 256u + ((uint32_t)(c ^ vswz) << 4), vrow + c * 4);
        }
        cpa_commit();
    }

    // ---- load Q tile 128x64 ----
    {
        const int r = tid >> 1;
        const int hb = (tid & 1) * 8;
        const float* qp = Q + ((size_t)(b * S_ + qt * 128 + r) * NH_ + h) * HD_ + hb * 4;
#pragma unroll
        for (int l = 0; l < 8; l++) {
            float4 v = *(const float4*)(qp + l * 4);
            *(float4*)(Qs + r * 64 + (((hb + l) ^ (r & 7)) << 2)) = v;
        }
    }

    float acc_o[8][4];
#pragma unroll
    for (int n8 = 0; n8 < 8; n8++)
#pragma unroll
        for (int e = 0; e < 4; e++) acc_o[n8][e] = 0.0f;
    float mA = -1e30f, mB = -1e30f, lA = 0.0f, lB = 0.0f;

    cpa_wait0();
    __syncthreads();

    const int ktmax = 2 * qt + 1;
    for (int kt = 0; kt <= ktmax; kt++) {
        const int buf = kt & 1;

        if (kt < ktmax) {
            const int nb = buf ^ 1;
            const float* krow = Kg + ((size_t)(b * S_ + (kt + 1) * 64 + cr) * NKV_ + kh) * HD_;
            const float* vsrc = vrow + (kt + 1) * 64;
#pragma unroll
            for (int l = 0; l < 4; l++) {
                const int c = cb + l;
                cpa16(ksb[nb] + crp * 256u + ((uint32_t)(c ^ kswz) << 4), krow + c * 4);
                cpa16(vtb[nb] + cr * 256u + ((uint32_t)(c ^ vswz) << 4), vsrc + c * 4);
            }
            cpa_commit();
        }

        float sacc[8][4];
#pragma unroll
        for (int nt = 0; nt < 8; nt++)
#pragma unroll
            for (int e = 0; e < 4; e++) sacc[nt][e] = 0.0f;
#pragma unroll
        for (int ks = 0; ks < 8; ks++) {
            unsigned qf[4];
            {
                const int row = wm + (sub & 1) * 8 + (lane & 7);
                const int kc = 2 * ks + (sub >> 1);
                ldsm4(qf, qsb + (uint32_t)(row * 64 + ((kc ^ (row & 7)) << 2)) * 4u);
            }
#pragma unroll
            for (int bp = 0; bp < 4; bp++) {
                unsigned kbf[4];
                const int row = bp * 16 + (sub >> 1) * 8 + (lane & 7);
                const int kc = 2 * ks + (sub & 1);
                ldsm4(kbf, ksb[buf] + (uint32_t)(row * 64 + ((kc ^ (row & 7)) << 2)) * 4u);
                mma8(sacc[bp * 2],     qf, kbf[0], kbf[1]);
                mma8(sacc[bp * 2 + 1], qf, kbf[2], kbf[3]);
            }
        }

        const int koff = kt * 64 - qt * 128;
        if (koff >= 0) {
            const int rA = wm + (lane >> 2);
            const int rB = rA + 8;
#pragma unroll
            for (int nt = 0; nt < 8; nt++) {
                const int k0 = koff + nt * 8 + (lane & 3);
                const int k1 = k0 + 4;
                if (k0 > rA) sacc[nt][0] = -1e30f;
                if (k1 > rA) sacc[nt][1] = -1e30f;
                if (k0 > rB) sacc[nt][2] = -1e30f;
                if (k1 > rB) sacc[nt][3] = -1e30f;
            }
        }

        {
            float hmA = -1e30f, hmB = -1e30f;
#pragma unroll
            for (int nt = 0; nt < 8; nt++) {
                hmA = fmaxf(hmA, fmaxf(sacc[nt][0], sacc[nt][1]));
                hmB = fmaxf(hmB, fmaxf(sacc[nt][2], sacc[nt][3]));
            }
            hmA = fmaxf(hmA, __shfl_xor_sync(~0u, hmA, 1));
            hmA = fmaxf(hmA, __shfl_xor_sync(~0u, hmA, 2));
            hmB = fmaxf(hmB, __shfl_xor_sync(~0u, hmB, 1));
            hmB = fmaxf(hmB, __shfl_xor_sync(~0u, hmB, 2));
            const float mnA = fmaxf(mA, hmA);
            const float mnB = fmaxf(mB, hmB);
            const float alA = __expf(mA - mnA);
            const float alB = __expf(mB - mnB);
            mA = mnA; mB = mnB;

            float hsA = 0.0f, hsB = 0.0f;
#pragma unroll
            for (int nt = 0; nt < 8; nt++) {
                const float p0 = __expf(sacc[nt][0] - mnA);
                const float p1 = __expf(sacc[nt][1] - mnA);
                const float p2 = __expf(sacc[nt][2] - mnB);
                const float p3 = __expf(sacc[nt][3] - mnB);
                hsA += p0 + p1; hsB += p2 + p3;
                sacc[nt][0] = __uint_as_float(tf32r(p0));
                sacc[nt][1] = __uint_as_float(tf32r(p1));
                sacc[nt][2] = __uint_as_float(tf32r(p2));
                sacc[nt][3] = __uint_as_float(tf32r(p3));
            }
            hsA += __shfl_xor_sync(~0u, hsA, 1); hsA += __shfl_xor_sync(~0u, hsA, 2);
            hsB += __shfl_xor_sync(~0u, hsB, 1); hsB += __shfl_xor_sync(~0u, hsB, 2);
            lA = lA * alA + hsA;
            lB = lB * alB + hsB;

#pragma unroll
            for (int n8 = 0; n8 < 8; n8++) {
                acc_o[n8][0] *= alA; acc_o[n8][1] *= alA;
                acc_o[n8][2] *= alB; acc_o[n8][3] *= alB;
            }
        }

#pragma unroll
        for (int jc = 0; jc < 8; jc++) {
            const unsigned* u = (const unsigned*)sacc[jc];
            const unsigned pa[4] = { u[0], u[2], u[1], u[3] };
#pragma unroll
            for (int bp = 0; bp < 4; bp++) {
                unsigned vb[4];
                const int d = bp * 16 + (sub >> 1) * 8 + (lane & 7);
                const int jj = 2 * jc + (sub & 1);
                const int ch = jj ^ (d & 7) ^ ((d >> 4) & 3);
                ldsm4(vb, vtb[buf] + (uint32_t)(d * 64 + (ch << 2)) * 4u);
                mma8(acc_o[bp * 2],     pa, vb[0], vb[1]);
                mma8(acc_o[bp * 2 + 1], pa, vb[2], vb[3]);
            }
        }

        cpa_wait0();
        __syncthreads();
    }

    // ---- epilogue: per-warp store, fp16 for the fp16 gemm2 ----
    {
        const int rA = wm + (lane >> 2);
        const int rB = rA + 8;
        const float liA = 1.0f / lA;
        const float liB = 1.0f / lB;
        __half* oA = O + (size_t)(b * S_ + qt * 128 + rA) * H_ + h * HD_ + (lane & 3) * 2;
        __half* oB = O + (size_t)(b * S_ + qt * 128 + rB) * H_ + h * HD_ + (lane & 3) * 2;
#pragma unroll
        for (int n8 = 0; n8 < 8; n8++) {
            __half2 ha, hb;
            ha.x = __float2half_rn(acc_o[n8][0] * liA);
            ha.y = __float2half_rn(acc_o[n8][1] * liA);
            hb.x = __float2half_rn(acc_o[n8][2] * liB);
            hb.y = __float2half_rn(acc_o[n8][3] * liB);
            *(__half2*)(oA + n8 * 8) = ha;
            *(__half2*)(oB + n8 * 8) = hb;
        }
    }
}

// ---------------- launch ----------------
extern "C" void kernel_launch(void* const* d_in, const int* in_sizes, int n_in,
                              void* d_out, int out_size)
{
    const int*   pos  = (const int*)d_in[0];
    const float* hid  = (const float*)d_in[1];
    const float* wqkv = (const float*)d_in[2];
    const float* qw   = (const float*)d_in[3];
    const float* kw   = (const float*)d_in[4];
    const float* wo   = (const float*)d_in[5];
    float* out = (float*)d_out;

    float *qkv, *q, *k, *v;
    __half *attnh, *hidh, *wqkvh, *woh;
    cudaGetSymbolAddress((void**)&qkv,   g_qkv);
    cudaGetSymbolAddress((void**)&q,     g_q);
    cudaGetSymbolAddress((void**)&k,     g_k);
    cudaGetSymbolAddress((void**)&v,     g_v);
    cudaGetSymbolAddress((void**)&attnh, g_attn_h);
    cudaGetSymbolAddress((void**)&hidh,  g_hid_h);
    cudaGetSymbolAddress((void**)&wqkvh, g_wqkv_h);
    cudaGetSymbolAddress((void**)&woh,   g_wo_h);

    cudaFuncSetAttribute(attn_mma4,
                         cudaFuncAttributeMaxDynamicSharedMemorySize, ATTN_SMEM_BYTES);

    // 0) convert GEMM operands to fp16 once
    const int n4_hid  = (BS_ * H_) / 4;
    const int n4_wqkv = (QKVN * H_) / 4;
    const int n4_wo   = (H_ * H_) / 4;
    round_half<<<(n4_hid  + 255) / 256, 256>>>(hid,  hidh,  n4_hid);
    round_half<<<(n4_wqkv + 255) / 256, 256>>>(wqkv, wqkvh, n4_wqkv);
    round_half<<<(n4_wo   + 255) / 256, 256>>>(wo,   woh,   n4_wo);

    // 1) qkv = hidden @ w_qkv^T   (fp16 mma, fp32 accum/out)
    dim3 g1(QKVN / 128, BS_ / 128);
    gemm_h<<<g1, 256>>>(hidh, wqkvh, qkv, BS_, QKVN, H_);

    // 2a) per-head LN + partial RoPE (tf32 outputs for attention)
    ln_rope<<<BS_ * 5, 256>>>(qkv, pos, qw, kw, q, k);
    // 2b) transpose V to [b][kh][d][s] (tf32)
    prep_v<<<dim3(S_ / 64, B_ * NKV_), 256>>>(qkv, v);

    // 3) causal GQA attention (tf32 flash v4; fp16 output)
    attn_mma4<<<dim3(S_ / 128, B_ * NH_), 256, ATTN_SMEM_BYTES>>>(q, k, v, attnh);

    // 4) out = attn @ w_o^T   (fp16 mma)
    dim3 g2(H_ / 128, BS_ / 128);
    gemm_h<<<g2, 256>>>(attnh, woh, out, BS_, H_, H_);
}

// round 16
// speedup vs baseline: 1.8028x; 1.2536x over previous
#include <cuda_runtime.h>
#include <cuda_fp16.h>
#include <cstdint>
#include <cstddef>

// Problem constants (fixed by setup_inputs)
#define B_   2
#define S_   2048
#define H_   2048
#define NH_  32
#define NKV_ 8
#define HD_  64
#define QKVN 3072
#define BS_  (B_ * S_)   // 4096

// ---------------- scratch (device globals: allocation-free) ----------------
__device__ __align__(16) float  g_qkv[(size_t)BS_ * QKVN];
__device__ __align__(16) __half g_qh[(size_t)BS_ * NH_ * HD_];     // fp16 Q (scaled)
__device__ __align__(16) __half g_kh[(size_t)BS_ * NKV_ * HD_];    // fp16 K
__device__ __align__(16) __half g_vh[(size_t)BS_ * NKV_ * HD_];    // fp16 V^T [b][kh][d][s]
__device__ __align__(16) __half g_attn_h[(size_t)BS_ * NH_ * HD_]; // fp16 attn out
__device__ __align__(16) __half g_hid_h[(size_t)BS_ * H_];
__device__ __align__(16) __half g_wqkv_h[(size_t)QKVN * H_];
__device__ __align__(16) __half g_wo_h[(size_t)H_ * H_];

// ---------------- helpers ----------------
__device__ __forceinline__ uint32_t smem_u32(const void* p) {
    uint32_t a;
    asm("{ .reg .u64 t; cvta.to.shared.u64 t, %1; cvt.u32.u64 %0, t; }" : "=r"(a) : "l"(p));
    return a;
}
// pack two fp32 -> f16x2 register (lo, hi)
__device__ __forceinline__ unsigned f2h2(float lo, float hi) {
    unsigned r;
    asm("cvt.rn.f16x2.f32 %0, %1, %2;" : "=r"(r) : "f"(hi), "f"(lo));
    return r;
}
// m16n8k16 fp16 mma, fp32 accumulate
__device__ __forceinline__ void mma16h(float* d, const unsigned* a, unsigned b0, unsigned b1) {
    asm volatile(
        "mma.sync.aligned.m16n8k16.row.col.f32.f16.f16.f32 "
        "{%0,%1,%2,%3}, {%4,%5,%6,%7}, {%8,%9}, {%0,%1,%2,%3};"
        : "+f"(d[0]), "+f"(d[1]), "+f"(d[2]), "+f"(d[3])
        : "r"(a[0]), "r"(a[1]), "r"(a[2]), "r"(a[3]), "r"(b0), "r"(b1));
}
__device__ __forceinline__ void ldsm4(unsigned* r, uint32_t addr) {
    asm volatile("ldmatrix.sync.aligned.m8n8.x4.shared.b16 {%0,%1,%2,%3}, [%4];"
                 : "=r"(r[0]), "=r"(r[1]), "=r"(r[2]), "=r"(r[3]) : "r"(addr));
}
__device__ __forceinline__ void cpa16(uint32_t dst, const void* src) {
    asm volatile("cp.async.cg.shared.global [%0], [%1], 16;" :: "r"(dst), "l"(src) : "memory");
}
__device__ __forceinline__ void cpa_commit() {
    asm volatile("cp.async.commit_group;" ::: "memory");
}
__device__ __forceinline__ void cpa_wait0() {
    asm volatile("cp.async.wait_group 0;" ::: "memory");
}
__device__ __forceinline__ void cpa_wait1() {
    asm volatile("cp.async.wait_group 1;" ::: "memory");
}

// ---------------- round_half: out = fp16(in), vectorized ----------------
__global__ __launch_bounds__(256) void round_half(
    const float* __restrict__ in, __half* __restrict__ out, int n4)
{
    const int i = blockIdx.x * 256 + threadIdx.x;
    if (i < n4) {
        float4 v = ((const float4*)in)[i];
        unsigned u0 = f2h2(v.x, v.y);
        unsigned u1 = f2h2(v.z, v.w);
        ((uint2*)out)[i] = make_uint2(u0, u1);
    }
}

// ================ fp16 mma GEMM: C = A[M,K] @ W[N,K]^T (fp32 out) ===========
// (unchanged from R15)
__device__ __forceinline__ uint32_t haddrA(uint32_t base, int m0, int ks, int lane) {
    int sub = lane >> 3;
    int row = m0 + (sub & 1) * 8 + (lane & 7);
    int c   = ks * 2 + (sub >> 1);
    return base + (uint32_t)(row * 64 + ((c ^ ((row >> 1) & 3)) << 4));
}
__device__ __forceinline__ uint32_t haddrB(uint32_t base, int n0, int ks, int lane) {
    int sub = lane >> 3;
    int row = n0 + (sub >> 1) * 8 + (lane & 7);
    int c   = ks * 2 + (sub & 1);
    return base + (uint32_t)(row * 64 + ((c ^ ((row >> 1) & 3)) << 4));
}

__global__ __launch_bounds__(256, 2) void gemm_h(
    const __half* __restrict__ A, const __half* __restrict__ W,
    float* __restrict__ C, int M, int N, int K)
{
    __shared__ __align__(16) __half As[3][128 * 32];
    __shared__ __align__(16) __half Bs[3][128 * 32];
    const uint32_t asb[3] = { smem_u32(As[0]), smem_u32(As[1]), smem_u32(As[2]) };
    const uint32_t bsb[3] = { smem_u32(Bs[0]), smem_u32(Bs[1]), smem_u32(Bs[2]) };

    const int tid = threadIdx.x, lane = tid & 31, wid = tid >> 5;
    const int bm = blockIdx.y * 128, bn = blockIdx.x * 128;
    const int wm = (wid & 1) * 64, wn = (wid >> 1) * 32;

    const int tr = tid >> 1;
    const int c0 = (tid & 1) * 2;
    const __half* Ap = A + (size_t)(bm + tr) * K + c0 * 8;
    const __half* Wp = W + (size_t)(bn + tr) * K + c0 * 8;
    uint32_t so[2];
#pragma unroll
    for (int l = 0; l < 2; l++)
        so[l] = (uint32_t)(tr * 64 + (((c0 + l) ^ ((tr >> 1) & 3)) << 4));

    float acc[16][4];
#pragma unroll
    for (int i = 0; i < 16; i++)
#pragma unroll
        for (int j = 0; j < 4; j++) acc[i][j] = 0.0f;

    const int T = K >> 5;

#pragma unroll
    for (int s = 0; s < 2; s++) {
        const __half* a = Ap + s * 32;
        const __half* w = Wp + s * 32;
#pragma unroll
        for (int l = 0; l < 2; l++) {
            cpa16(asb[s] + so[l], a + l * 8);
            cpa16(bsb[s] + so[l], w + l * 8);
        }
        cpa_commit();
    }

    for (int t = 0; t < T; t++) {
        cpa_wait1();
        __syncthreads();

        if (t + 2 < T) {
            const int s = (t + 2) % 3;
            const __half* a = Ap + (t + 2) * 32;
            const __half* w = Wp + (t + 2) * 32;
#pragma unroll
            for (int l = 0; l < 2; l++) {
                cpa16(asb[s] + so[l], a + l * 8);
                cpa16(bsb[s] + so[l], w + l * 8);
            }
            cpa_commit();
        }

        const int buf = t % 3;
#pragma unroll
        for (int ks = 0; ks < 2; ks++) {
            unsigned af[4][4], bf[2][4];
#pragma unroll
            for (int mt = 0; mt < 4; mt++)
                ldsm4(af[mt], haddrA(asb[buf], wm + mt * 16, ks, lane));
#pragma unroll
            for (int bp = 0; bp < 2; bp++)
                ldsm4(bf[bp], haddrB(bsb[buf], wn + bp * 16, ks, lane));
#pragma unroll
            for (int mt = 0; mt < 4; mt++)
#pragma unroll
                for (int bp = 0; bp < 2; bp++) {
                    mma16h(acc[mt * 4 + bp * 2],     af[mt], bf[bp][0], bf[bp][1]);
                    mma16h(acc[mt * 4 + bp * 2 + 1], af[mt], bf[bp][2], bf[bp][3]);
                }
        }
    }

#pragma unroll
    for (int mt = 0; mt < 4; mt++) {
        const int rA = bm + wm + mt * 16 + (lane >> 2);
        float* cA = C + (size_t)rA * N + bn + wn + (lane & 3) * 2;
        float* cB = cA + 8 * (size_t)N;
#pragma unroll
        for (int nt = 0; nt < 4; nt++) {
            *(float2*)(cA + nt * 8) = make_float2(acc[mt * 4 + nt][0], acc[mt * 4 + nt][1]);
            *(float2*)(cB + nt * 8) = make_float2(acc[mt * 4 + nt][2], acc[mt * 4 + nt][3]);
        }
    }
}

// ---------------- fused per-head LayerNorm + partial NeoX RoPE (fp16 out) ----
__global__ __launch_bounds__(256) void ln_rope(
    const float* __restrict__ qkv, const int* __restrict__ pos_ids,
    const float* __restrict__ qw, const float* __restrict__ kw,
    __half* __restrict__ qo, __half* __restrict__ ko)
{
    const int wid = threadIdx.x >> 5;
    const int lane = threadIdx.x & 31;
    const int bs = blockIdx.x / 5;
    const int head = (blockIdx.x % 5) * 8 + wid;   // 0..39 (32 Q + 8 K)

    const float* src = qkv + (size_t)bs * QKVN + head * HD_;
    float v0 = src[lane], v1 = src[lane + 32];

    float s = v0 + v1;
#pragma unroll
    for (int m = 16; m; m >>= 1) s += __shfl_xor_sync(~0u, s, m);
    const float mu = s * (1.0f / 64.0f);
    const float d0 = v0 - mu, d1 = v1 - mu;
    float vs = d0 * d0 + d1 * d1;
#pragma unroll
    for (int m = 16; m; m >>= 1) vs += __shfl_xor_sync(~0u, vs, m);
    const float inv = rsqrtf(vs * (1.0f / 64.0f) + 1e-5f);

    const float* w = (head < NH_) ? (qw + head * HD_) : (kw + (head - NH_) * HD_);
    float n0 = d0 * inv * w[lane];
    float n1 = d1 * inv * w[lane + 32];

    const float p = (float)pos_ids[bs];
    const float partner = __shfl_xor_sync(~0u, n0, 8);
    if (lane < 16) {
        const int i = lane & 7;
        const float invf = powf(10000.0f, -(float)i * 0.125f);
        const float ang = p * invf;
        const float c = cosf(ang), sn = sinf(ang);
        n0 = (lane < 8) ? (n0 * c - partner * sn) : (n0 * c + partner * sn);
    }
    const float sc = (head < NH_) ? 0.125f : 1.0f;   // HEAD_DIM^-0.5 folded into Q

    if (head < NH_) {
        __half* dst = qo + ((size_t)bs * NH_ + head) * HD_;
        dst[lane] = __float2half_rn(n0 * sc);
        dst[lane + 32] = __float2half_rn(n1 * sc);
    } else {
        __half* dst = ko + ((size_t)bs * NKV_ + (head - NH_)) * HD_;
        dst[lane] = __float2half_rn(n0);
        dst[lane + 32] = __float2half_rn(n1);
    }
}

// ---------------- prep_v: transpose V to fp16 [b][kh][d][s] ----------------
__global__ __launch_bounds__(256) void prep_v(
    const float* __restrict__ qkv, __half* __restrict__ V)
{
    __shared__ float ts[64][65];
    const int bkh = blockIdx.y;             // 0..15
    const int b = bkh >> 3, kh = bkh & 7;
    const int s0 = blockIdx.x * 64;
    const int r  = threadIdx.x >> 2;        // 0..63
    const int c0 = (threadIdx.x & 3) * 16;

    const float* src = qkv + (size_t)(b * S_ + s0 + r) * QKVN + 2560 + kh * 64 + c0;
#pragma unroll
    for (int l = 0; l < 4; l++) {
        float4 v = *(const float4*)(src + l * 4);
        ts[r][c0 + l * 4 + 0] = v.x;
        ts[r][c0 + l * 4 + 1] = v.y;
        ts[r][c0 + l * 4 + 2] = v.z;
        ts[r][c0 + l * 4 + 3] = v.w;
    }
    __syncthreads();

    const int d  = threadIdx.x >> 2;
    const int sc = (threadIdx.x & 3) * 16;
    __half* dst = V + ((size_t)(b * NKV_ + kh) * HD_ + d) * S_ + s0 + sc;
#pragma unroll
    for (int l = 0; l < 4; l++) {
        unsigned u0 = f2h2(ts[sc + l * 4 + 0][d], ts[sc + l * 4 + 1][d]);
        unsigned u1 = f2h2(ts[sc + l * 4 + 2][d], ts[sc + l * 4 + 3][d]);
        *(uint2*)(dst + l * 4) = make_uint2(u0, u1);
    }
}

// ======================= flash attention v5 (fp16 mma) =======================
// CTA: 128 q-rows x (b,h); KV tiles of 64 double-buffered via cp.async.
// 8 warps, warp owns 16 rows x all 64 keys; warp-local softmax; 1 sync/tile.
// All operands fp16 (fp32 accum/softmax). The S accumulator feeds PV A-frags
// by direct f16x2 packing (c0/c1 are consecutive key cols = A-frag half2):
//   a0=h2(c0,c1)[tile 2jc], a1=h2(c2,c3)[2jc], a2/a3 same of tile 2jc+1.
// No K-row permutation needed. Smem rows = 64 halfs (128B), swizzle c^(row&7).
// smem: Qs [128][64]h @0 (16KB); Ks[2] @16384/24576; Vt[2] @32768/40960 (48KB)
#define ATTN_SMEM_BYTES 49152

__global__ __launch_bounds__(256, 2) void attn_mma5(
    const __half* __restrict__ Q, const __half* __restrict__ Kg,
    const __half* __restrict__ Vg, __half* __restrict__ O)
{
    extern __shared__ __align__(16) char smraw[];
    const uint32_t qsb = smem_u32(smraw);
    const uint32_t ksb[2] = { qsb + 16384u, qsb + 24576u };
    const uint32_t vtb[2] = { qsb + 32768u, qsb + 40960u };

    const int qt = (int)gridDim.x - 1 - (int)blockIdx.x;    // heavy tiles first
    const int bh = blockIdx.y;
    const int b = bh >> 5, h = bh & 31, kh = h >> 2;
    const int tid = threadIdx.x, lane = tid & 31, wid = tid >> 5;
    const int wm = wid * 16;
    const int sub = lane >> 3;

    // KV loader: row cr (0..63), chunks cb2, cb2+1 (16B = 8 halfs each)
    const int cr = tid >> 2;
    const int cb2 = (tid & 3) * 2;
    const uint32_t rsw = (uint32_t)(cr & 7);
    const __half* vrow = Vg + ((size_t)(b * NKV_ + kh) * HD_ + cr) * S_;

    // ---- issue KV tile 0 + Q tile in one group ----
    {
        const __half* krow = Kg + ((size_t)(b * S_ + cr) * NKV_ + kh) * HD_;
#pragma unroll
        for (int l = 0; l < 2; l++) {
            const int c = cb2 + l;
            cpa16(ksb[0] + cr * 128u + ((uint32_t)(c ^ rsw) << 4), krow + c * 8);
            cpa16(vtb[0] + cr * 128u + ((uint32_t)(c ^ rsw) << 4), vrow + c * 8);
        }
        const int qr = tid >> 1;
        const int qc0 = (tid & 1) * 4;
        const __half* qp = Q + ((size_t)(b * S_ + qt * 128 + qr) * NH_ + h) * HD_;
#pragma unroll
        for (int l = 0; l < 4; l++) {
            const int c = qc0 + l;
            cpa16(qsb + qr * 128u + ((uint32_t)(c ^ (qr & 7)) << 4), qp + c * 8);
        }
        cpa_commit();
    }

    float acc_o[8][4];
#pragma unroll
    for (int n8 = 0; n8 < 8; n8++)
#pragma unroll
        for (int e = 0; e < 4; e++) acc_o[n8][e] = 0.0f;
    float mA = -1e30f, mB = -1e30f, lA = 0.0f, lB = 0.0f;

    cpa_wait0();
    __syncthreads();   // Qs + KV tile 0 visible

    const int ktmax = 2 * qt + 1;
    for (int kt = 0; kt <= ktmax; kt++) {
        const int buf = kt & 1;

        // ---- prefetch tile kt+1 ----
        if (kt < ktmax) {
            const int nb = buf ^ 1;
            const __half* krow = Kg + ((size_t)(b * S_ + (kt + 1) * 64 + cr) * NKV_ + kh) * HD_;
            const __half* vsrc = vrow + (kt + 1) * 64;
#pragma unroll
            for (int l = 0; l < 2; l++) {
                const int c = cb2 + l;
                cpa16(ksb[nb] + cr * 128u + ((uint32_t)(c ^ rsw) << 4), krow + c * 8);
                cpa16(vtb[nb] + cr * 128u + ((uint32_t)(c ^ rsw) << 4), vsrc + c * 8);
            }
            cpa_commit();
        }

        // ---- S = Q @ K^T (warp: 16 rows x 64 keys; 4 K16 steps) ----
        float sacc[8][4];
#pragma unroll
        for (int nt = 0; nt < 8; nt++)
#pragma unroll
            for (int e = 0; e < 4; e++) sacc[nt][e] = 0.0f;
#pragma unroll
        for (int ks = 0; ks < 4; ks++) {
            unsigned qf[4];
            {
                const int row = wm + (sub & 1) * 8 + (lane & 7);
                const int c = 2 * ks + (sub >> 1);
                ldsm4(qf, qsb + (uint32_t)(row * 128 + ((c ^ (row & 7)) << 4)));
            }
#pragma unroll
            for (int bp = 0; bp < 4; bp++) {
                unsigned kbf[4];
                const int row = bp * 16 + (sub >> 1) * 8 + (lane & 7);
                const int c = 2 * ks + (sub & 1);
                ldsm4(kbf, ksb[buf] + (uint32_t)(row * 128 + ((c ^ (row & 7)) << 4)));
                mma16h(sacc[bp * 2],     qf, kbf[0], kbf[1]);
                mma16h(sacc[bp * 2 + 1], qf, kbf[2], kbf[3]);
            }
        }

        // ---- causal mask (natural cols: c0 -> key nt*8+2t, c1 -> +1) ----
        const int koff = kt * 64 - qt * 128;
        if (koff >= 0) {
            const int rA = wm + (lane >> 2);
            const int rB = rA + 8;
#pragma unroll
            for (int nt = 0; nt < 8; nt++) {
                const int k0 = koff + nt * 8 + (lane & 3) * 2;
                const int k1 = k0 + 1;
                if (k0 > rA) sacc[nt][0] = -1e30f;
                if (k1 > rA) sacc[nt][1] = -1e30f;
                if (k0 > rB) sacc[nt][2] = -1e30f;
                if (k1 > rB) sacc[nt][3] = -1e30f;
            }
        }

        // ---- warp-local online softmax ----
        {
            float hmA = -1e30f, hmB = -1e30f;
#pragma unroll
            for (int nt = 0; nt < 8; nt++) {
                hmA = fmaxf(hmA, fmaxf(sacc[nt][0], sacc[nt][1]));
                hmB = fmaxf(hmB, fmaxf(sacc[nt][2], sacc[nt][3]));
            }
            hmA = fmaxf(hmA, __shfl_xor_sync(~0u, hmA, 1));
            hmA = fmaxf(hmA, __shfl_xor_sync(~0u, hmA, 2));
            hmB = fmaxf(hmB, __shfl_xor_sync(~0u, hmB, 1));
            hmB = fmaxf(hmB, __shfl_xor_sync(~0u, hmB, 2));
            const float mnA = fmaxf(mA, hmA);
            const float mnB = fmaxf(mB, hmB);
            const float alA = __expf(mA - mnA);
            const float alB = __expf(mB - mnB);
            mA = mnA; mB = mnB;

            float hsA = 0.0f, hsB = 0.0f;
#pragma unroll
            for (int nt = 0; nt < 8; nt++) {
                const float p0 = __expf(sacc[nt][0] - mnA);
                const float p1 = __expf(sacc[nt][1] - mnA);
                const float p2 = __expf(sacc[nt][2] - mnB);
                const float p3 = __expf(sacc[nt][3] - mnB);
                hsA += p0 + p1; hsB += p2 + p3;
                sacc[nt][0] = p0; sacc[nt][1] = p1;
                sacc[nt][2] = p2; sacc[nt][3] = p3;
            }
            hsA += __shfl_xor_sync(~0u, hsA, 1); hsA += __shfl_xor_sync(~0u, hsA, 2);
            hsB += __shfl_xor_sync(~0u, hsB, 1); hsB += __shfl_xor_sync(~0u, hsB, 2);
            lA = lA * alA + hsA;
            lB = lB * alB + hsB;

#pragma unroll
            for (int n8 = 0; n8 < 8; n8++) {
                acc_o[n8][0] *= alA; acc_o[n8][1] *= alA;
                acc_o[n8][2] *= alB; acc_o[n8][3] *= alB;
            }
        }

        // ---- O += P @ V (P packed from registers; 4 K16 steps) ----
#pragma unroll
        for (int jc = 0; jc < 4; jc++) {
            const unsigned pa[4] = {
                f2h2(sacc[2 * jc][0],     sacc[2 * jc][1]),
                f2h2(sacc[2 * jc][2],     sacc[2 * jc][3]),
                f2h2(sacc[2 * jc + 1][0], sacc[2 * jc + 1][1]),
                f2h2(sacc[2 * jc + 1][2], sacc[2 * jc + 1][3])
            };
#pragma unroll
            for (int bp = 0; bp < 4; bp++) {
                unsigned vb[4];
                const int d = bp * 16 + (sub >> 1) * 8 + (lane & 7);
                const int c = 2 * jc + (sub & 1);
                ldsm4(vb, vtb[buf] + (uint32_t)(d * 128 + ((c ^ (d & 7)) << 4)));
                mma16h(acc_o[bp * 2],     pa, vb[0], vb[1]);
                mma16h(acc_o[bp * 2 + 1], pa, vb[2], vb[3]);
            }
        }

        cpa_wait0();
        __syncthreads();   // tile kt+1 landed AND all warps done with buf
    }

    // ---- epilogue: per-warp store, fp16 for the fp16 gemm2 ----
    {
        const int rA = wm + (lane >> 2);
        const int rB = rA + 8;
        const float liA = 1.0f / lA;
        const float liB = 1.0f / lB;
        __half* oA = O + (size_t)(b * S_ + qt * 128 + rA) * H_ + h * HD_ + (lane & 3) * 2;
        __half* oB = O + (size_t)(b * S_ + qt * 128 + rB) * H_ + h * HD_ + (lane & 3) * 2;
#pragma unroll
        for (int n8 = 0; n8 < 8; n8++) {
            *(unsigned*)(oA + n8 * 8) = f2h2(acc_o[n8][0] * liA, acc_o[n8][1] * liA);
            *(unsigned*)(oB + n8 * 8) = f2h2(acc_o[n8][2] * liB, acc_o[n8][3] * liB);
        }
    }
}

// ---------------- launch ----------------
extern "C" void kernel_launch(void* const* d_in, const int* in_sizes, int n_in,
                              void* d_out, int out_size)
{
    const int*   pos  = (const int*)d_in[0];
    const float* hid  = (const float*)d_in[1];
    const float* wqkv = (const float*)d_in[2];
    const float* qw   = (const float*)d_in[3];
    const float* kw   = (const float*)d_in[4];
    const float* wo   = (const float*)d_in[5];
    float* out = (float*)d_out;

    float *qkv;
    __half *qh, *kh_, *vh, *attnh, *hidh, *wqkvh, *woh;
    cudaGetSymbolAddress((void**)&qkv,   g_qkv);
    cudaGetSymbolAddress((void**)&qh,    g_qh);
    cudaGetSymbolAddress((void**)&kh_,   g_kh);
    cudaGetSymbolAddress((void**)&vh,    g_vh);
    cudaGetSymbolAddress((void**)&attnh, g_attn_h);
    cudaGetSymbolAddress((void**)&hidh,  g_hid_h);
    cudaGetSymbolAddress((void**)&wqkvh, g_wqkv_h);
    cudaGetSymbolAddress((void**)&woh,   g_wo_h);

    cudaFuncSetAttribute(attn_mma5,
                         cudaFuncAttributeMaxDynamicSharedMemorySize, ATTN_SMEM_BYTES);

    // 0) convert GEMM operands to fp16 once
    const int n4_hid  = (BS_ * H_) / 4;
    const int n4_wqkv = (QKVN * H_) / 4;
    const int n4_wo   = (H_ * H_) / 4;
    round_half<<<(n4_hid  + 255) / 256, 256>>>(hid,  hidh,  n4_hid);
    round_half<<<(n4_wqkv + 255) / 256, 256>>>(wqkv, wqkvh, n4_wqkv);
    round_half<<<(n4_wo   + 255) / 256, 256>>>(wo,   woh,   n4_wo);

    // 1) qkv = hidden @ w_qkv^T   (fp16 mma, fp32 accum/out)
    dim3 g1(QKVN / 128, BS_ / 128);
    gemm_h<<<g1, 256>>>(hidh, wqkvh, qkv, BS_, QKVN, H_);

    // 2a) per-head LN + partial RoPE (fp16 out, scale folded into Q)
    ln_rope<<<BS_ * 5, 256>>>(qkv, pos, qw, kw, qh, kh_);
    // 2b) transpose V to fp16 [b][kh][d][s]
    prep_v<<<dim3(S_ / 64, B_ * NKV_), 256>>>(qkv, vh);

    // 3) causal GQA attention (fp16 mma flash v5)
    attn_mma5<<<dim3(S_ / 128, B_ * NH_), 256, ATTN_SMEM_BYTES>>>(qh, kh_, vh, attnh);

    // 4) out = attn @ w_o^T   (fp16 mma)
    dim3 g2(H_ / 128, BS_ / 128);
    gemm_h<<<g2, 256>>>(attnh, woh, out, BS_, H_, H_);
}

// round 17
// speedup vs baseline: 1.8035x; 1.0004x over previous
#include <cuda_runtime.h>
#include <cuda_fp16.h>
#include <cstdint>
#include <cstddef>

// Problem constants (fixed by setup_inputs)
#define B_   2
#define S_   2048
#define H_   2048
#define NH_  32
#define NKV_ 8
#define HD_  64
#define QKVN 3072
#define BS_  (B_ * S_)   // 4096

// ---------------- scratch (device globals: allocation-free) ----------------
__device__ __align__(16) __half g_qkv_h[(size_t)BS_ * QKVN];       // fp16 qkv
__device__ __align__(16) __half g_qh[(size_t)BS_ * NH_ * HD_];     // fp16 Q (scaled)
__device__ __align__(16) __half g_kh[(size_t)BS_ * NKV_ * HD_];    // fp16 K
__device__ __align__(16) __half g_vh[(size_t)BS_ * NKV_ * HD_];    // fp16 V^T [b][kh][d][s]
__device__ __align__(16) __half g_attn_h[(size_t)BS_ * NH_ * HD_]; // fp16 attn out
__device__ __align__(16) __half g_hid_h[(size_t)BS_ * H_];
__device__ __align__(16) __half g_wqkv_h[(size_t)QKVN * H_];
__device__ __align__(16) __half g_wo_h[(size_t)H_ * H_];

// ---------------- helpers ----------------
__device__ __forceinline__ uint32_t smem_u32(const void* p) {
    uint32_t a;
    asm("{ .reg .u64 t; cvta.to.shared.u64 t, %1; cvt.u32.u64 %0, t; }" : "=r"(a) : "l"(p));
    return a;
}
// pack two fp32 -> f16x2 register (lo, hi)
__device__ __forceinline__ unsigned f2h2(float lo, float hi) {
    unsigned r;
    asm("cvt.rn.f16x2.f32 %0, %1, %2;" : "=r"(r) : "f"(hi), "f"(lo));
    return r;
}
// m16n8k16 fp16 mma, fp32 accumulate
__device__ __forceinline__ void mma16h(float* d, const unsigned* a, unsigned b0, unsigned b1) {
    asm volatile(
        "mma.sync.aligned.m16n8k16.row.col.f32.f16.f16.f32 "
        "{%0,%1,%2,%3}, {%4,%5,%6,%7}, {%8,%9}, {%0,%1,%2,%3};"
        : "+f"(d[0]), "+f"(d[1]), "+f"(d[2]), "+f"(d[3])
        : "r"(a[0]), "r"(a[1]), "r"(a[2]), "r"(a[3]), "r"(b0), "r"(b1));
}
__device__ __forceinline__ void ldsm4(unsigned* r, uint32_t addr) {
    asm volatile("ldmatrix.sync.aligned.m8n8.x4.shared.b16 {%0,%1,%2,%3}, [%4];"
                 : "=r"(r[0]), "=r"(r[1]), "=r"(r[2]), "=r"(r[3]) : "r"(addr));
}
__device__ __forceinline__ void cpa16(uint32_t dst, const void* src) {
    asm volatile("cp.async.cg.shared.global [%0], [%1], 16;" :: "r"(dst), "l"(src) : "memory");
}
__device__ __forceinline__ void cpa_commit() {
    asm volatile("cp.async.commit_group;" ::: "memory");
}
__device__ __forceinline__ void cpa_wait0() {
    asm volatile("cp.async.wait_group 0;" ::: "memory");
}
__device__ __forceinline__ void cpa_wait1() {
    asm volatile("cp.async.wait_group 1;" ::: "memory");
}

// ---------------- round_half: out = fp16(in), vectorized ----------------
__global__ __launch_bounds__(256) void round_half(
    const float* __restrict__ in, __half* __restrict__ out, int n4)
{
    const int i = blockIdx.x * 256 + threadIdx.x;
    if (i < n4) {
        float4 v = ((const float4*)in)[i];
        unsigned u0 = f2h2(v.x, v.y);
        unsigned u1 = f2h2(v.z, v.w);
        ((uint2*)out)[i] = make_uint2(u0, u1);
    }
}

// ================ fp16 mma GEMM core (shared by fp32/fp16-out) ==============
__device__ __forceinline__ uint32_t haddrA(uint32_t base, int m0, int ks, int lane) {
    int sub = lane >> 3;
    int row = m0 + (sub & 1) * 8 + (lane & 7);
    int c   = ks * 2 + (sub >> 1);
    return base + (uint32_t)(row * 64 + ((c ^ ((row >> 1) & 3)) << 4));
}
__device__ __forceinline__ uint32_t haddrB(uint32_t base, int n0, int ks, int lane) {
    int sub = lane >> 3;
    int row = n0 + (sub >> 1) * 8 + (lane & 7);
    int c   = ks * 2 + (sub & 1);
    return base + (uint32_t)(row * 64 + ((c ^ ((row >> 1) & 3)) << 4));
}

// computes the 128x128 CTA tile into acc[16][4]; returns warp coords
struct GemmCore {
    int wm, wn, lane;
};
__device__ __forceinline__ void gemm_core(
    const __half* __restrict__ A, const __half* __restrict__ W,
    int M, int N, int K, float acc[16][4], GemmCore& gc,
    __half As[3][128 * 32], __half Bs[3][128 * 32])
{
    const uint32_t asb[3] = { smem_u32(As[0]), smem_u32(As[1]), smem_u32(As[2]) };
    const uint32_t bsb[3] = { smem_u32(Bs[0]), smem_u32(Bs[1]), smem_u32(Bs[2]) };

    const int tid = threadIdx.x, lane = tid & 31, wid = tid >> 5;
    const int bm = blockIdx.y * 128, bn = blockIdx.x * 128;
    gc.wm = (wid & 1) * 64; gc.wn = (wid >> 1) * 32; gc.lane = lane;

    const int tr = tid >> 1;
    const int c0 = (tid & 1) * 2;
    const __half* Ap = A + (size_t)(bm + tr) * K + c0 * 8;
    const __half* Wp = W + (size_t)(bn + tr) * K + c0 * 8;
    uint32_t so[2];
#pragma unroll
    for (int l = 0; l < 2; l++)
        so[l] = (uint32_t)(tr * 64 + (((c0 + l) ^ ((tr >> 1) & 3)) << 4));

#pragma unroll
    for (int i = 0; i < 16; i++)
#pragma unroll
        for (int j = 0; j < 4; j++) acc[i][j] = 0.0f;

    const int T = K >> 5;

#pragma unroll
    for (int s = 0; s < 2; s++) {
        const __half* a = Ap + s * 32;
        const __half* w = Wp + s * 32;
#pragma unroll
        for (int l = 0; l < 2; l++) {
            cpa16(asb[s] + so[l], a + l * 8);
            cpa16(bsb[s] + so[l], w + l * 8);
        }
        cpa_commit();
    }

    for (int t = 0; t < T; t++) {
        cpa_wait1();
        __syncthreads();

        if (t + 2 < T) {
            const int s = (t + 2) % 3;
            const __half* a = Ap + (t + 2) * 32;
            const __half* w = Wp + (t + 2) * 32;
#pragma unroll
            for (int l = 0; l < 2; l++) {
                cpa16(asb[s] + so[l], a + l * 8);
                cpa16(bsb[s] + so[l], w + l * 8);
            }
            cpa_commit();
        }

        const int buf = t % 3;
#pragma unroll
        for (int ks = 0; ks < 2; ks++) {
            unsigned af[4][4], bf[2][4];
#pragma unroll
            for (int mt = 0; mt < 4; mt++)
                ldsm4(af[mt], haddrA(asb[buf], gc.wm + mt * 16, ks, lane));
#pragma unroll
            for (int bp = 0; bp < 2; bp++)
                ldsm4(bf[bp], haddrB(bsb[buf], gc.wn + bp * 16, ks, lane));
#pragma unroll
            for (int mt = 0; mt < 4; mt++)
#pragma unroll
                for (int bp = 0; bp < 2; bp++) {
                    mma16h(acc[mt * 4 + bp * 2],     af[mt], bf[bp][0], bf[bp][1]);
                    mma16h(acc[mt * 4 + bp * 2 + 1], af[mt], bf[bp][2], bf[bp][3]);
                }
        }
    }
}

// fp32-out version (final output projection)
__global__ __launch_bounds__(256, 2) void gemm_h(
    const __half* __restrict__ A, const __half* __restrict__ W,
    float* __restrict__ C, int M, int N, int K)
{
    __shared__ __align__(16) __half As[3][128 * 32];
    __shared__ __align__(16) __half Bs[3][128 * 32];
    float acc[16][4];
    GemmCore gc;
    gemm_core(A, W, M, N, K, acc, gc, As, Bs);

    const int bm = blockIdx.y * 128, bn = blockIdx.x * 128;
#pragma unroll
    for (int mt = 0; mt < 4; mt++) {
        const int rA = bm + gc.wm + mt * 16 + (gc.lane >> 2);
        float* cA = C + (size_t)rA * N + bn + gc.wn + (gc.lane & 3) * 2;
        float* cB = cA + 8 * (size_t)N;
#pragma unroll
        for (int nt = 0; nt < 4; nt++) {
            *(float2*)(cA + nt * 8) = make_float2(acc[mt * 4 + nt][0], acc[mt * 4 + nt][1]);
            *(float2*)(cB + nt * 8) = make_float2(acc[mt * 4 + nt][2], acc[mt * 4 + nt][3]);
        }
    }
}

// fp16-out version (qkv projection)
__global__ __launch_bounds__(256, 2) void gemm_h16(
    const __half* __restrict__ A, const __half* __restrict__ W,
    __half* __restrict__ C, int M, int N, int K)
{
    __shared__ __align__(16) __half As[3][128 * 32];
    __shared__ __align__(16) __half Bs[3][128 * 32];
    float acc[16][4];
    GemmCore gc;
    gemm_core(A, W, M, N, K, acc, gc, As, Bs);

    const int bm = blockIdx.y * 128, bn = blockIdx.x * 128;
#pragma unroll
    for (int mt = 0; mt < 4; mt++) {
        const int rA = bm + gc.wm + mt * 16 + (gc.lane >> 2);
        __half* cA = C + (size_t)rA * N + bn + gc.wn + (gc.lane & 3) * 2;
        __half* cB = cA + 8 * (size_t)N;
#pragma unroll
        for (int nt = 0; nt < 4; nt++) {
            *(unsigned*)(cA + nt * 8) = f2h2(acc[mt * 4 + nt][0], acc[mt * 4 + nt][1]);
            *(unsigned*)(cB + nt * 8) = f2h2(acc[mt * 4 + nt][2], acc[mt * 4 + nt][3]);
        }
    }
}

// ------------- fused per-head LayerNorm + partial NeoX RoPE (fp16 io) --------
__global__ __launch_bounds__(256) void ln_rope(
    const __half* __restrict__ qkv, const int* __restrict__ pos_ids,
    const float* __restrict__ qw, const float* __restrict__ kw,
    __half* __restrict__ qo, __half* __restrict__ ko)
{
    const int wid = threadIdx.x >> 5;
    const int lane = threadIdx.x & 31;
    const int bs = blockIdx.x / 5;
    const int head = (blockIdx.x % 5) * 8 + wid;   // 0..39 (32 Q + 8 K)

    const __half* src = qkv + (size_t)bs * QKVN + head * HD_;
    float v0 = __half2float(src[lane]), v1 = __half2float(src[lane + 32]);

    float s = v0 + v1;
#pragma unroll
    for (int m = 16; m; m >>= 1) s += __shfl_xor_sync(~0u, s, m);
    const float mu = s * (1.0f / 64.0f);
    const float d0 = v0 - mu, d1 = v1 - mu;
    float vs = d0 * d0 + d1 * d1;
#pragma unroll
    for (int m = 16; m; m >>= 1) vs += __shfl_xor_sync(~0u, vs, m);
    const float inv = rsqrtf(vs * (1.0f / 64.0f) + 1e-5f);

    const float* w = (head < NH_) ? (qw + head * HD_) : (kw + (head - NH_) * HD_);
    float n0 = d0 * inv * w[lane];
    float n1 = d1 * inv * w[lane + 32];

    const float p = (float)pos_ids[bs];
    const float partner = __shfl_xor_sync(~0u, n0, 8);
    if (lane < 16) {
        const int i = lane & 7;
        const float invf = powf(10000.0f, -(float)i * 0.125f);
        const float ang = p * invf;
        const float c = cosf(ang), sn = sinf(ang);
        n0 = (lane < 8) ? (n0 * c - partner * sn) : (n0 * c + partner * sn);
    }
    const float sc = (head < NH_) ? 0.125f : 1.0f;   // HEAD_DIM^-0.5 folded into Q

    if (head < NH_) {
        __half* dst = qo + ((size_t)bs * NH_ + head) * HD_;
        dst[lane] = __float2half_rn(n0 * sc);
        dst[lane + 32] = __float2half_rn(n1 * sc);
    } else {
        __half* dst = ko + ((size_t)bs * NKV_ + (head - NH_)) * HD_;
        dst[lane] = __float2half_rn(n0);
        dst[lane + 32] = __float2half_rn(n1);
    }
}

// ---------------- prep_v: transpose fp16 V to [b][kh][d][s] ----------------
__global__ __launch_bounds__(256) void prep_v(
    const __half* __restrict__ qkv, __half* __restrict__ V)
{
    __shared__ __half ts[64][72];       // pad 8 halfs -> column reads spread banks
    const int bkh = blockIdx.y;         // 0..15
    const int b = bkh >> 3, kh = bkh & 7;
    const int s0 = blockIdx.x * 64;
    const int r  = threadIdx.x >> 2;    // 0..63
    const int c0 = (threadIdx.x & 3) * 16;

    const __half* src = qkv + (size_t)(b * S_ + s0 + r) * QKVN + 2560 + kh * 64 + c0;
#pragma unroll
    for (int l = 0; l < 2; l++)
        *(uint4*)&ts[r][c0 + l * 8] = *(const uint4*)(src + l * 8);
    __syncthreads();

    const int d  = threadIdx.x >> 2;
    const int sc = (threadIdx.x & 3) * 16;
    __half* dst = V + ((size_t)(b * NKV_ + kh) * HD_ + d) * S_ + s0 + sc;
#pragma unroll
    for (int l = 0; l < 4; l++) {
        __half2 h0, h1;
        h0.x = ts[sc + l * 4 + 0][d]; h0.y = ts[sc + l * 4 + 1][d];
        h1.x = ts[sc + l * 4 + 2][d]; h1.y = ts[sc + l * 4 + 3][d];
        *(__half2*)(dst + l * 4) = h0;
        *(__half2*)(dst + l * 4 + 2) = h1;
    }
}

// ======================= flash attention v5 (fp16 mma) =======================
// (unchanged from R16)
#define ATTN_SMEM_BYTES 49152

__global__ __launch_bounds__(256, 2) void attn_mma5(
    const __half* __restrict__ Q, const __half* __restrict__ Kg,
    const __half* __restrict__ Vg, __half* __restrict__ O)
{
    extern __shared__ __align__(16) char smraw[];
    const uint32_t qsb = smem_u32(smraw);
    const uint32_t ksb[2] = { qsb + 16384u, qsb + 24576u };
    const uint32_t vtb[2] = { qsb + 32768u, qsb + 40960u };

    const int qt = (int)gridDim.x - 1 - (int)blockIdx.x;    // heavy tiles first
    const int bh = blockIdx.y;
    const int b = bh >> 5, h = bh & 31, kh = h >> 2;
    const int tid = threadIdx.x, lane = tid & 31, wid = tid >> 5;
    const int wm = wid * 16;
    const int sub = lane >> 3;

    const int cr = tid >> 2;
    const int cb2 = (tid & 3) * 2;
    const uint32_t rsw = (uint32_t)(cr & 7);
    const __half* vrow = Vg + ((size_t)(b * NKV_ + kh) * HD_ + cr) * S_;

    // ---- issue KV tile 0 + Q tile in one group ----
    {
        const __half* krow = Kg + ((size_t)(b * S_ + cr) * NKV_ + kh) * HD_;
#pragma unroll
        for (int l = 0; l < 2; l++) {
            const int c = cb2 + l;
            cpa16(ksb[0] + cr * 128u + ((uint32_t)(c ^ rsw) << 4), krow + c * 8);
            cpa16(vtb[0] + cr * 128u + ((uint32_t)(c ^ rsw) << 4), vrow + c * 8);
        }
        const int qr = tid >> 1;
        const int qc0 = (tid & 1) * 4;
        const __half* qp = Q + ((size_t)(b * S_ + qt * 128 + qr) * NH_ + h) * HD_;
#pragma unroll
        for (int l = 0; l < 4; l++) {
            const int c = qc0 + l;
            cpa16(qsb + qr * 128u + ((uint32_t)(c ^ (qr & 7)) << 4), qp + c * 8);
        }
        cpa_commit();
    }

    float acc_o[8][4];
#pragma unroll
    for (int n8 = 0; n8 < 8; n8++)
#pragma unroll
        for (int e = 0; e < 4; e++) acc_o[n8][e] = 0.0f;
    float mA = -1e30f, mB = -1e30f, lA = 0.0f, lB = 0.0f;

    cpa_wait0();
    __syncthreads();

    const int ktmax = 2 * qt + 1;
    for (int kt = 0; kt <= ktmax; kt++) {
        const int buf = kt & 1;

        if (kt < ktmax) {
            const int nb = buf ^ 1;
            const __half* krow = Kg + ((size_t)(b * S_ + (kt + 1) * 64 + cr) * NKV_ + kh) * HD_;
            const __half* vsrc = vrow + (kt + 1) * 64;
#pragma unroll
            for (int l = 0; l < 2; l++) {
                const int c = cb2 + l;
                cpa16(ksb[nb] + cr * 128u + ((uint32_t)(c ^ rsw) << 4), krow + c * 8);
                cpa16(vtb[nb] + cr * 128u + ((uint32_t)(c ^ rsw) << 4), vsrc + c * 8);
            }
            cpa_commit();
        }

        float sacc[8][4];
#pragma unroll
        for (int nt = 0; nt < 8; nt++)
#pragma unroll
            for (int e = 0; e < 4; e++) sacc[nt][e] = 0.0f;
#pragma unroll
        for (int ks = 0; ks < 4; ks++) {
            unsigned qf[4];
            {
                const int row = wm + (sub & 1) * 8 + (lane & 7);
                const int c = 2 * ks + (sub >> 1);
                ldsm4(qf, qsb + (uint32_t)(row * 128 + ((c ^ (row & 7)) << 4)));
            }
#pragma unroll
            for (int bp = 0; bp < 4; bp++) {
                unsigned kbf[4];
                const int row = bp * 16 + (sub >> 1) * 8 + (lane & 7);
                const int c = 2 * ks + (sub & 1);
                ldsm4(kbf, ksb[buf] + (uint32_t)(row * 128 + ((c ^ (row & 7)) << 4)));
                mma16h(sacc[bp * 2],     qf, kbf[0], kbf[1]);
                mma16h(sacc[bp * 2 + 1], qf, kbf[2], kbf[3]);
            }
        }

        const int koff = kt * 64 - qt * 128;
        if (koff >= 0) {
            const int rA = wm + (lane >> 2);
            const int rB = rA + 8;
#pragma unroll
            for (int nt = 0; nt < 8; nt++) {
                const int k0 = koff + nt * 8 + (lane & 3) * 2;
                const int k1 = k0 + 1;
                if (k0 > rA) sacc[nt][0] = -1e30f;
                if (k1 > rA) sacc[nt][1] = -1e30f;
                if (k0 > rB) sacc[nt][2] = -1e30f;
                if (k1 > rB) sacc[nt][3] = -1e30f;
            }
        }

        {
            float hmA = -1e30f, hmB = -1e30f;
#pragma unroll
            for (int nt = 0; nt < 8; nt++) {
                hmA = fmaxf(hmA, fmaxf(sacc[nt][0], sacc[nt][1]));
                hmB = fmaxf(hmB, fmaxf(sacc[nt][2], sacc[nt][3]));
            }
            hmA = fmaxf(hmA, __shfl_xor_sync(~0u, hmA, 1));
            hmA = fmaxf(hmA, __shfl_xor_sync(~0u, hmA, 2));
            hmB = fmaxf(hmB, __shfl_xor_sync(~0u, hmB, 1));
            hmB = fmaxf(hmB, __shfl_xor_sync(~0u, hmB, 2));
            const float mnA = fmaxf(mA, hmA);
            const float mnB = fmaxf(mB, hmB);
            const float alA = __expf(mA - mnA);
            const float alB = __expf(mB - mnB);
            mA = mnA; mB = mnB;

            float hsA = 0.0f, hsB = 0.0f;
#pragma unroll
            for (int nt = 0; nt < 8; nt++) {
                const float p0 = __expf(sacc[nt][0] - mnA);
                const float p1 = __expf(sacc[nt][1] - mnA);
                const float p2 = __expf(sacc[nt][2] - mnB);
                const float p3 = __expf(sacc[nt][3] - mnB);
                hsA += p0 + p1; hsB += p2 + p3;
                sacc[nt][0] = p0; sacc[nt][1] = p1;
                sacc[nt][2] = p2; sacc[nt][3] = p3;
            }
            hsA += __shfl_xor_sync(~0u, hsA, 1); hsA += __shfl_xor_sync(~0u, hsA, 2);
            hsB += __shfl_xor_sync(~0u, hsB, 1); hsB += __shfl_xor_sync(~0u, hsB, 2);
            lA = lA * alA + hsA;
            lB = lB * alB + hsB;

#pragma unroll
            for (int n8 = 0; n8 < 8; n8++) {
                acc_o[n8][0] *= alA; acc_o[n8][1] *= alA;
                acc_o[n8][2] *= alB; acc_o[n8][3] *= alB;
            }
        }

#pragma unroll
        for (int jc = 0; jc < 4; jc++) {
            const unsigned pa[4] = {
                f2h2(sacc[2 * jc][0],     sacc[2 * jc][1]),
                f2h2(sacc[2 * jc][2],     sacc[2 * jc][3]),
                f2h2(sacc[2 * jc + 1][0], sacc[2 * jc + 1][1]),
                f2h2(sacc[2 * jc + 1][2], sacc[2 * jc + 1][3])
            };
#pragma unroll
            for (int bp = 0; bp < 4; bp++) {
                unsigned vb[4];
                const int d = bp * 16 + (sub >> 1) * 8 + (lane & 7);
                const int c = 2 * jc + (sub & 1);
                ldsm4(vb, vtb[buf] + (uint32_t)(d * 128 + ((c ^ (d & 7)) << 4)));
                mma16h(acc_o[bp * 2],     pa, vb[0], vb[1]);
                mma16h(acc_o[bp * 2 + 1], pa, vb[2], vb[3]);
            }
        }

        cpa_wait0();
        __syncthreads();
    }

    // ---- epilogue: per-warp store, fp16 ----
    {
        const int rA = wm + (lane >> 2);
        const int rB = rA + 8;
        const float liA = 1.0f / lA;
        const float liB = 1.0f / lB;
        __half* oA = O + (size_t)(b * S_ + qt * 128 + rA) * H_ + h * HD_ + (lane & 3) * 2;
        __half* oB = O + (size_t)(b * S_ + qt * 128 + rB) * H_ + h * HD_ + (lane & 3) * 2;
#pragma unroll
        for (int n8 = 0; n8 < 8; n8++) {
            *(unsigned*)(oA + n8 * 8) = f2h2(acc_o[n8][0] * liA, acc_o[n8][1] * liA);
            *(unsigned*)(oB + n8 * 8) = f2h2(acc_o[n8][2] * liB, acc_o[n8][3] * liB);
        }
    }
}

// ---------------- launch ----------------
extern "C" void kernel_launch(void* const* d_in, const int* in_sizes, int n_in,
                              void* d_out, int out_size)
{
    const int*   pos  = (const int*)d_in[0];
    const float* hid  = (const float*)d_in[1];
    const float* wqkv = (const float*)d_in[2];
    const float* qw   = (const float*)d_in[3];
    const float* kw   = (const float*)d_in[4];
    const float* wo   = (const float*)d_in[5];
    float* out = (float*)d_out;

    __half *qkvh, *qh, *kh_, *vh, *attnh, *hidh, *wqkvh, *woh;
    cudaGetSymbolAddress((void**)&qkvh,  g_qkv_h);
    cudaGetSymbolAddress((void**)&qh,    g_qh);
    cudaGetSymbolAddress((void**)&kh_,   g_kh);
    cudaGetSymbolAddress((void**)&vh,    g_vh);
    cudaGetSymbolAddress((void**)&attnh, g_attn_h);
    cudaGetSymbolAddress((void**)&hidh,  g_hid_h);
    cudaGetSymbolAddress((void**)&wqkvh, g_wqkv_h);
    cudaGetSymbolAddress((void**)&woh,   g_wo_h);

    cudaFuncSetAttribute(attn_mma5,
                         cudaFuncAttributeMaxDynamicSharedMemorySize, ATTN_SMEM_BYTES);

    // 0) convert GEMM operands to fp16 once
    const int n4_hid  = (BS_ * H_) / 4;
    const int n4_wqkv = (QKVN * H_) / 4;
    const int n4_wo   = (H_ * H_) / 4;
    round_half<<<(n4_hid  + 255) / 256, 256>>>(hid,  hidh,  n4_hid);
    round_half<<<(n4_wqkv + 255) / 256, 256>>>(wqkv, wqkvh, n4_wqkv);
    round_half<<<(n4_wo   + 255) / 256, 256>>>(wo,   woh,   n4_wo);

    // 1) qkv = hidden @ w_qkv^T   (fp16 out)
    dim3 g1(QKVN / 128, BS_ / 128);
    gemm_h16<<<g1, 256>>>(hidh, wqkvh, qkvh, BS_, QKVN, H_);

    // 2a) per-head LN + partial RoPE (fp16 in/out, scale folded into Q)
    ln_rope<<<BS_ * 5, 256>>>(qkvh, pos, qw, kw, qh, kh_);
    // 2b) transpose fp16 V to [b][kh][d][s]
    prep_v<<<dim3(S_ / 64, B_ * NKV_), 256>>>(qkvh, vh);

    // 3) causal GQA attention (fp16 mma flash v5)
    attn_mma5<<<dim3(S_ / 128, B_ * NH_), 256, ATTN_SMEM_BYTES>>>(qh, kh_, vh, attnh);

    // 4) out = attn @ w_o^T   (fp32 out)
    dim3 g2(H_ / 128, BS_ / 128);
    gemm_h<<<g2, 256>>>(attnh, woh, out, BS_, H_, H_);
}